// round 14
// baseline (speedup 1.0000x reference)
#include <cuda_runtime.h>
#include <cuda_bf16.h>
#include <cuda_fp16.h>
#include <cstdint>

#define N_MAX 100000
#define E_MAX 1250000

// ---------------- scratch (static device allocations; no runtime alloc) -----
__device__ int    g_is64;
__device__ int    g_deg[N_MAX];
__device__ int    g_incl[N_MAX];
__device__ int    g_rowptr[N_MAX];
__device__ int    g_cursor[N_MAX];
__device__ int    g_bsum[256];
__device__ float  g_dinv[N_MAX];   // rsqrt(indeg+1)  (GCN)
__device__ float  g_cinv[N_MAX];   // 1/max(indeg,1)  (SAGE mean)
__device__ int    g_edge[E_MAX];   // src index, bucketed by dst
__device__ float  g_buf[6][(size_t)N_MAX * 64];
__device__ __half g_half[3][(size_t)N_MAX * 64];   // xh (N*64) + g1s1 interleaved (N*128)

// ---------------- fused: zero degrees + x->fp16 + dtype detection ------------
__global__ void k_prep(const void* __restrict__ ei, const float* __restrict__ x,
                       __half* __restrict__ xh, int e, int n) {
    int i = blockIdx.x * blockDim.x + threadIdx.x;
    if (i < n) g_deg[i] = 0;
    int total = n * 16;   // float4 quads
    if (i < total) {
        float4 v = ((const float4*)x)[i];
        __half2 h0 = __floats2half2_rn(v.x, v.y);
        __half2 h1 = __floats2half2_rn(v.z, v.w);
        ((__half2*)xh)[i * 2]     = h0;
        ((__half2*)xh)[i * 2 + 1] = h1;
    }
    if (blockIdx.x == 0) {
        __shared__ int bad;
        if (threadIdx.x == 0) bad = 0;
        __syncthreads();
        const long long* p = (const long long*)ei;
        int m = e < 2048 ? e : 2048;
        for (int j = threadIdx.x; j < m; j += blockDim.x) {
            long long v = p[j];
            if (v < 0 || v >= (long long)n) bad = 1;
        }
        __syncthreads();
        if (threadIdx.x == 0) g_is64 = bad ? 0 : 1;
    }
}

__device__ __forceinline__ int ld_idx(const void* __restrict__ ei, int is64,
                                      long long pos, int n) {
    long long v = is64 ? ((const long long*)ei)[pos]
                       : (long long)((const int*)ei)[pos];
    int s = (int)v;
    if ((unsigned)s >= (unsigned)n) s = 0;   // trap-safety clamp
    return s;
}

// ---------------- CSR build --------------------------------------------------
__global__ void k_count(const void* __restrict__ ei, int e, int n) {
    int i = blockIdx.x * blockDim.x + threadIdx.x;
    if (i >= e) return;
    int is64 = g_is64;
    int d = ld_idx(ei, is64, (long long)e + i, n);
    atomicAdd(&g_deg[d], 1);
}

__global__ void k_scan1(int n) {  // per-block inclusive scan (1024/block)
    __shared__ int sh[1024];
    int t = threadIdx.x;
    int i = blockIdx.x * 1024 + t;
    int v = (i < n) ? g_deg[i] : 0;
    sh[t] = v;
    __syncthreads();
    for (int off = 1; off < 1024; off <<= 1) {
        int add = (t >= off) ? sh[t - off] : 0;
        __syncthreads();
        sh[t] += add;
        __syncthreads();
    }
    if (i < n) g_incl[i] = sh[t];
    if (t == 1023) g_bsum[blockIdx.x] = sh[1023];
}

// fused scan2+scan3: every block redundantly scans the <=256 block sums in smem
__global__ void k_scan23(int n, int nb) {
    __shared__ int sh[256];
    __shared__ int orig[256];
    int t = threadIdx.x;
    if (t < 256) {
        int v = (t < nb) ? g_bsum[t] : 0;
        sh[t] = v;
        orig[t] = v;
    }
    __syncthreads();
    for (int off = 1; off < 256; off <<= 1) {
        int add = (t < 256 && t >= off) ? sh[t - off] : 0;
        __syncthreads();
        if (t < 256) sh[t] += add;
        __syncthreads();
    }
    int i = blockIdx.x * 1024 + t;
    if (i >= n) return;
    int boff = sh[blockIdx.x] - orig[blockIdx.x];  // exclusive prefix of this block
    int d  = g_deg[i];
    int rp = g_incl[i] - d + boff;
    g_rowptr[i] = rp;
    g_cursor[i] = rp;
    g_dinv[i] = rsqrtf((float)d + 1.0f);
    g_cinv[i] = 1.0f / fmaxf((float)d, 1.0f);
}

__global__ void k_scatter(const void* __restrict__ ei, int e, int n) {
    int i = blockIdx.x * blockDim.x + threadIdx.x;
    if (i >= e) return;
    int is64 = g_is64;
    int s = ld_idx(ei, is64, i, n);
    int d = ld_idx(ei, is64, (long long)e + i, n);
    int pos = atomicAdd(&g_cursor[d], 1);
    g_edge[pos] = s;
}

// ---------------- wide-lane dual aggregations (warp per node) ----------------
// Lane split: lanes 0-15 accumulate the GCN-weighted sum, lanes 16-31 the mean.
// Each lane owns 4 feature columns; one LDG.64 per edge covers the row(s).
// Edge idx + dinv loaded 8-wide and shfl-broadcast.

// dual1: source xh rows [64 halves, stride 64]; both half-warps read same row.
__global__ void k_agg_dual1(const __half* __restrict__ xh,
                            float* __restrict__ outG, float* __restrict__ outM, int n) {
    int gw   = (blockIdx.x * blockDim.x + threadIdx.x) >> 5;
    int lane = threadIdx.x & 31;
    if (gw >= n) return;
    int start = g_rowptr[gw];
    int cnt   = g_deg[gw];
    int half  = lane >> 4;   // 0 = weighted, 1 = mean
    int pos   = lane & 15;   // columns 4*pos .. 4*pos+3
    float a0 = 0.f, a1 = 0.f, a2 = 0.f, a3 = 0.f;
    for (int eb = 0; eb < cnt; eb += 8) {
        int m = cnt - eb; if (m > 8) m = 8;
        int idx = 0; float ds = 0.f;
        if (lane < m) { idx = g_edge[start + eb + lane]; ds = g_dinv[idx]; }
        for (int j = 0; j < m; j++) {
            int   cur = __shfl_sync(0xffffffffu, idx, j);
            float dsj = __shfl_sync(0xffffffffu, ds, j);
            float w   = half ? 1.0f : dsj;
            float2 raw = *(const float2*)(xh + (size_t)cur * 64 + pos * 4);
            float2 f01 = __half22float2(*(__half2*)&raw.x);
            float2 f23 = __half22float2(*(__half2*)&raw.y);
            a0 = fmaf(w, f01.x, a0);
            a1 = fmaf(w, f01.y, a1);
            a2 = fmaf(w, f23.x, a2);
            a3 = fmaf(w, f23.y, a3);
        }
    }
    float dd = g_dinv[gw];
    if (half == 0) {
        float2 raw = *(const float2*)(xh + (size_t)gw * 64 + pos * 4);
        float2 s01 = __half22float2(*(__half2*)&raw.x);
        float2 s23 = __half22float2(*(__half2*)&raw.y);
        float sw = dd * dd;
        float4 og = make_float4(fmaf(dd, a0, sw * s01.x), fmaf(dd, a1, sw * s01.y),
                                fmaf(dd, a2, sw * s23.x), fmaf(dd, a3, sw * s23.y));
        *(float4*)(outG + (size_t)gw * 64 + pos * 4) = og;
    } else {
        float ci = g_cinv[gw];
        *(float4*)(outM + (size_t)gw * 64 + pos * 4) =
            make_float4(a0 * ci, a1 * ci, a2 * ci, a3 * ci);
    }
}

// dual2: source interleaved g1|s1 rows [128 halves, stride 128]:
// halves [0,64) = g1 (GCN source), [64,128) = s1 (mean source).
// lane l reads halves 4l..4l+3: lanes 0-15 -> g1, lanes 16-31 -> s1. One LDG.64/edge.
__global__ void k_agg_dual2(const __half* __restrict__ gs,
                            float* __restrict__ outG, float* __restrict__ outM, int n) {
    int gw   = (blockIdx.x * blockDim.x + threadIdx.x) >> 5;
    int lane = threadIdx.x & 31;
    if (gw >= n) return;
    int start = g_rowptr[gw];
    int cnt   = g_deg[gw];
    int half  = lane >> 4;
    int pos   = lane & 15;
    float a0 = 0.f, a1 = 0.f, a2 = 0.f, a3 = 0.f;
    for (int eb = 0; eb < cnt; eb += 8) {
        int m = cnt - eb; if (m > 8) m = 8;
        int idx = 0; float ds = 0.f;
        if (lane < m) { idx = g_edge[start + eb + lane]; ds = g_dinv[idx]; }
        for (int j = 0; j < m; j++) {
            int   cur = __shfl_sync(0xffffffffu, idx, j);
            float dsj = __shfl_sync(0xffffffffu, ds, j);
            float w   = half ? 1.0f : dsj;
            float2 raw = *(const float2*)(gs + (size_t)cur * 128 + lane * 4);
            float2 f01 = __half22float2(*(__half2*)&raw.x);
            float2 f23 = __half22float2(*(__half2*)&raw.y);
            a0 = fmaf(w, f01.x, a0);
            a1 = fmaf(w, f01.y, a1);
            a2 = fmaf(w, f23.x, a2);
            a3 = fmaf(w, f23.y, a3);
        }
    }
    float dd = g_dinv[gw];
    if (half == 0) {
        float2 raw = *(const float2*)(gs + (size_t)gw * 128 + pos * 4);  // self g1
        float2 s01 = __half22float2(*(__half2*)&raw.x);
        float2 s23 = __half22float2(*(__half2*)&raw.y);
        float sw = dd * dd;
        float4 og = make_float4(fmaf(dd, a0, sw * s01.x), fmaf(dd, a1, sw * s01.y),
                                fmaf(dd, a2, sw * s23.x), fmaf(dd, a3, sw * s23.y));
        *(float4*)(outG + (size_t)gw * 64 + pos * 4) = og;
    } else {
        float ci = g_cinv[gw];
        *(float4*)(outM + (size_t)gw * 64 + pos * 4) =
            make_float4(a0 * ci, a1 * ci, a2 * ci, a3 * ci);
    }
}

// ---------------- tensor-core GEMM via split-bf16 (3-term) -------------------
__device__ __forceinline__ void mma_bf16(float* c,
                                         uint32_t a0, uint32_t a1, uint32_t a2, uint32_t a3,
                                         uint32_t b0, uint32_t b1) {
    asm volatile(
        "mma.sync.aligned.m16n8k16.row.col.f32.bf16.bf16.f32 "
        "{%0,%1,%2,%3}, {%4,%5,%6,%7}, {%8,%9}, {%0,%1,%2,%3};\n"
        : "+f"(c[0]), "+f"(c[1]), "+f"(c[2]), "+f"(c[3])
        : "r"(a0), "r"(a1), "r"(a2), "r"(a3), "r"(b0), "r"(b1));
}

__device__ __forceinline__ void split_pack(float x, float y, uint32_t& hi, uint32_t& lo) {
    __nv_bfloat162 h = __floats2bfloat162_rn(x, y);
    __nv_bfloat162 l = __floats2bfloat162_rn(x - __bfloat162float(h.x),
                                             y - __bfloat162float(h.y));
    hi = *(uint32_t*)&h;
    lo = *(uint32_t*)&l;
}

// Y = act( Xa@Wa [+ Xb@Wb] + bias ).  Xa fp32 (stride 64); Xb fp32/fp16 stride xbs;
// Y fp32/fp16 with row stride os.
template <bool DUAL, bool RELU, bool XB_HALF, bool OUT_HALF>
__global__ void k_gemm(const float* __restrict__ Xa, const float* __restrict__ Wa,
                       const void* __restrict__ Xb, const float* __restrict__ Wb,
                       const float* __restrict__ bias, void* __restrict__ Yv,
                       int n, int xbs, int os) {
    constexpr int KT  = DUAL ? 128 : 64;
    constexpr int KP  = KT + 8;
    constexpr int KPW = KP / 2;
    extern __shared__ uint32_t smu[];
    uint32_t* Ahi = smu;
    uint32_t* Alo = Ahi + 128 * KPW;
    uint32_t* Bhi = Alo + 128 * KPW;
    uint32_t* Blo = Bhi + 64 * KPW;

    int tid  = threadIdx.x;
    int base = blockIdx.x * 128;

    __nv_bfloat16* BhiH = (__nv_bfloat16*)Bhi;
    __nv_bfloat16* BloH = (__nv_bfloat16*)Blo;
    for (int i = tid; i < KT * 16; i += 256) {
        int k = i >> 4, c = (i & 15) << 2;
        const float* wsrc = (DUAL && k >= 64) ? (Wb + (size_t)(k - 64) * 64 + c)
                                              : (Wa + (size_t)k * 64 + c);
        float4 v = *(const float4*)wsrc;
        float vv[4] = {v.x, v.y, v.z, v.w};
#pragma unroll
        for (int j = 0; j < 4; j++) {
            __nv_bfloat16 h = __float2bfloat16_rn(vv[j]);
            BhiH[(c + j) * KP + k] = h;
            BloH[(c + j) * KP + k] = __float2bfloat16_rn(vv[j] - __bfloat162float(h));
        }
    }
    constexpr int KQ4 = KT / 4;
    for (int i = tid; i < 128 * KQ4; i += 256) {
        int r  = i / KQ4;
        int kq = i % KQ4;
        int row = base + r;
        float4 v = make_float4(0.f, 0.f, 0.f, 0.f);
        if (row < n) {
            int k = kq * 4;
            if (DUAL && k >= 64) {
                if (XB_HALF) {
                    const __half* xb = (const __half*)Xb + (size_t)row * xbs + (k - 64);
                    float2 fa = __half22float2(*(const __half2*)xb);
                    float2 fb = __half22float2(*(const __half2*)(xb + 2));
                    v = make_float4(fa.x, fa.y, fb.x, fb.y);
                } else {
                    v = *(const float4*)((const float*)Xb + (size_t)row * xbs + (k - 64));
                }
            } else {
                v = *(const float4*)(Xa + (size_t)row * 64 + k);
            }
        }
        uint32_t h0, l0, h1, l1;
        split_pack(v.x, v.y, h0, l0);
        split_pack(v.z, v.w, h1, l1);
        int wo = r * KPW + kq * 2;
        Ahi[wo]     = h0;
        Ahi[wo + 1] = h1;
        Alo[wo]     = l0;
        Alo[wo + 1] = l1;
    }
    __syncthreads();

    int warp  = tid >> 5;
    int lane  = tid & 31;
    int tq    = lane >> 2;
    int tc    = lane & 3;
    int rbase = warp * 16;

    float acc[8][4];
#pragma unroll
    for (int nt = 0; nt < 8; nt++)
#pragma unroll
        for (int c = 0; c < 4; c++) acc[nt][c] = 0.f;

#pragma unroll
    for (int kk = 0; kk < KT / 16; kk++) {
        int colw = kk * 8 + tc;
        int ra = (rbase + tq) * KPW + colw;
        int rb = ra + 8 * KPW;
        uint32_t ah0 = Ahi[ra], ah1 = Ahi[rb], ah2 = Ahi[ra + 4], ah3 = Ahi[rb + 4];
        uint32_t al0 = Alo[ra], al1 = Alo[rb], al2 = Alo[ra + 4], al3 = Alo[rb + 4];
#pragma unroll
        for (int nt = 0; nt < 8; nt++) {
            int nb = (nt * 8 + tq) * KPW + colw;
            uint32_t bh0 = Bhi[nb], bh1 = Bhi[nb + 4];
            uint32_t bl0 = Blo[nb], bl1 = Blo[nb + 4];
            mma_bf16(acc[nt], ah0, ah1, ah2, ah3, bh0, bh1);
            mma_bf16(acc[nt], ah0, ah1, ah2, ah3, bl0, bl1);
            mma_bf16(acc[nt], al0, al1, al2, al3, bh0, bh1);
        }
    }

    int r0 = base + rbase + tq;
    int r1 = r0 + 8;
#pragma unroll
    for (int nt = 0; nt < 8; nt++) {
        int col = nt * 8 + 2 * tc;
        float2 bv = *(const float2*)&bias[col];
        float2 o0 = make_float2(acc[nt][0] + bv.x, acc[nt][1] + bv.y);
        float2 o1 = make_float2(acc[nt][2] + bv.x, acc[nt][3] + bv.y);
        if (RELU) {
            o0.x = fmaxf(o0.x, 0.f); o0.y = fmaxf(o0.y, 0.f);
            o1.x = fmaxf(o1.x, 0.f); o1.y = fmaxf(o1.y, 0.f);
        }
        if (OUT_HALF) {
            __half* Y = (__half*)Yv;
            if (r0 < n) *(__half2*)&Y[(size_t)r0 * os + col] = __floats2half2_rn(o0.x, o0.y);
            if (r1 < n) *(__half2*)&Y[(size_t)r1 * os + col] = __floats2half2_rn(o1.x, o1.y);
        } else {
            float* Y = (float*)Yv;
            if (r0 < n) *(float2*)&Y[(size_t)r0 * os + col] = o0;
            if (r1 < n) *(float2*)&Y[(size_t)r1 * os + col] = o1;
        }
    }
}

// ---------------- projection GEMM with fused per-branch LayerNorm -----------
__global__ void k_proj(const float* __restrict__ G, const float* __restrict__ S,
                       const float* __restrict__ gg, const float* __restrict__ gb,
                       const float* __restrict__ sg, const float* __restrict__ sb,
                       const float* __restrict__ W, const float* __restrict__ bias,
                       float* __restrict__ Y, int n) {
    constexpr int KT = 128, KP = 136, KPW = 68;
    extern __shared__ uint32_t smu[];
    uint32_t* Ahi = smu;
    uint32_t* Alo = Ahi + 128 * KPW;
    uint32_t* Bhi = Alo + 128 * KPW;
    uint32_t* Blo = Bhi + 64 * KPW;

    int tid  = threadIdx.x;
    int warp = tid >> 5;
    int lane = tid & 31;
    int base = blockIdx.x * 128;

    __nv_bfloat16* BhiH = (__nv_bfloat16*)Bhi;
    __nv_bfloat16* BloH = (__nv_bfloat16*)Blo;
    for (int i = tid; i < 128 * 16; i += 256) {
        int k = i >> 4, c = (i & 15) << 2;
        float4 v = *(const float4*)(W + (size_t)k * 64 + c);
        float vv[4] = {v.x, v.y, v.z, v.w};
#pragma unroll
        for (int j = 0; j < 4; j++) {
            __nv_bfloat16 h = __float2bfloat16_rn(vv[j]);
            BhiH[(c + j) * KP + k] = h;
            BloH[(c + j) * KP + k] = __float2bfloat16_rn(vv[j] - __bfloat162float(h));
        }
    }

    float2 ggv = *(const float2*)&gg[lane * 2];
    float2 gbv = *(const float2*)&gb[lane * 2];
    float2 sgv = *(const float2*)&sg[lane * 2];
    float2 sbv = *(const float2*)&sb[lane * 2];
    for (int it = 0; it < 16; it++) {
        int r   = warp * 16 + it;
        int row = base + r;
        float2 gv = make_float2(0.f, 0.f), sv = make_float2(0.f, 0.f);
        if (row < n) {
            gv = *(const float2*)(G + (size_t)row * 64 + lane * 2);
            sv = *(const float2*)(S + (size_t)row * 64 + lane * 2);
        }
        float sgm = gv.x + gv.y, qg = gv.x * gv.x + gv.y * gv.y;
        float ssm = sv.x + sv.y, qs = sv.x * sv.x + sv.y * sv.y;
#pragma unroll
        for (int o = 16; o > 0; o >>= 1) {
            sgm += __shfl_xor_sync(0xffffffffu, sgm, o);
            qg  += __shfl_xor_sync(0xffffffffu, qg, o);
            ssm += __shfl_xor_sync(0xffffffffu, ssm, o);
            qs  += __shfl_xor_sync(0xffffffffu, qs, o);
        }
        float mug  = sgm * (1.0f / 64.0f);
        float varg = fmaxf(qg * (1.0f / 64.0f) - mug * mug, 0.f);
        float rg   = rsqrtf(varg + 1e-5f);
        float mus  = ssm * (1.0f / 64.0f);
        float vars = fmaxf(qs * (1.0f / 64.0f) - mus * mus, 0.f);
        float rs   = rsqrtf(vars + 1e-5f);
        float ogx = (gv.x - mug) * rg * ggv.x + gbv.x;
        float ogy = (gv.y - mug) * rg * ggv.y + gbv.y;
        float osx = (sv.x - mus) * rs * sgv.x + sbv.x;
        float osy = (sv.y - mus) * rs * sgv.y + sbv.y;
        uint32_t h, l;
        split_pack(ogx, ogy, h, l);
        Ahi[r * KPW + lane] = h;
        Alo[r * KPW + lane] = l;
        split_pack(osx, osy, h, l);
        Ahi[r * KPW + 32 + lane] = h;
        Alo[r * KPW + 32 + lane] = l;
    }
    __syncthreads();

    int tq    = lane >> 2;
    int tc    = lane & 3;
    int rbase = warp * 16;

    float acc[8][4];
#pragma unroll
    for (int nt = 0; nt < 8; nt++)
#pragma unroll
        for (int c = 0; c < 4; c++) acc[nt][c] = 0.f;

#pragma unroll
    for (int kk = 0; kk < KT / 16; kk++) {
        int colw = kk * 8 + tc;
        int ra = (rbase + tq) * KPW + colw;
        int rb = ra + 8 * KPW;
        uint32_t ah0 = Ahi[ra], ah1 = Ahi[rb], ah2 = Ahi[ra + 4], ah3 = Ahi[rb + 4];
        uint32_t al0 = Alo[ra], al1 = Alo[rb], al2 = Alo[ra + 4], al3 = Alo[rb + 4];
#pragma unroll
        for (int nt = 0; nt < 8; nt++) {
            int nb = (nt * 8 + tq) * KPW + colw;
            uint32_t bh0 = Bhi[nb], bh1 = Bhi[nb + 4];
            uint32_t bl0 = Blo[nb], bl1 = Blo[nb + 4];
            mma_bf16(acc[nt], ah0, ah1, ah2, ah3, bh0, bh1);
            mma_bf16(acc[nt], ah0, ah1, ah2, ah3, bl0, bl1);
            mma_bf16(acc[nt], al0, al1, al2, al3, bh0, bh1);
        }
    }

    int r0 = base + rbase + tq;
    int r1 = r0 + 8;
#pragma unroll
    for (int nt = 0; nt < 8; nt++) {
        int col = nt * 8 + 2 * tc;
        float2 bv = *(const float2*)&bias[col];
        float2 o0 = make_float2(acc[nt][0] + bv.x, acc[nt][1] + bv.y);
        float2 o1 = make_float2(acc[nt][2] + bv.x, acc[nt][3] + bv.y);
        if (r0 < n) *(float2*)&Y[(size_t)r0 * 64 + col] = o0;
        if (r1 < n) *(float2*)&Y[(size_t)r1 * 64 + col] = o1;
    }
}

// ---------------- launcher ---------------------------------------------------
extern "C" void kernel_launch(void* const* d_in, const int* in_sizes, int n_in,
                              void* d_out, int out_size) {
    const float* x        = (const float*)d_in[0];
    const void*  ei       = d_in[1];                 // int64 or int32; auto-detected
    const float* gcn_w1   = (const float*)d_in[2];
    const float* gcn_b1   = (const float*)d_in[3];
    const float* gcn_w2   = (const float*)d_in[4];
    const float* gcn_b2   = (const float*)d_in[5];
    const float* sage_wl1 = (const float*)d_in[6];
    const float* sage_bl1 = (const float*)d_in[7];
    const float* sage_wr1 = (const float*)d_in[8];
    const float* sage_wl2 = (const float*)d_in[9];
    const float* sage_bl2 = (const float*)d_in[10];
    const float* sage_wr2 = (const float*)d_in[11];
    const float* gln_g    = (const float*)d_in[12];
    const float* gln_b    = (const float*)d_in[13];
    const float* sln_g    = (const float*)d_in[14];
    const float* sln_b    = (const float*)d_in[15];
    const float* proj_w   = (const float*)d_in[16];
    const float* proj_b   = (const float*)d_in[17];
    float*       out      = (float*)d_out;

    int n = in_sizes[0] / 64;
    int e = in_sizes[1] / 2;

    float* bufbase = nullptr;
    cudaGetSymbolAddress((void**)&bufbase, g_buf);
    float* B[6];
    for (int i = 0; i < 6; i++) B[i] = bufbase + (size_t)i * N_MAX * 64;
    __half* halfbase = nullptr;
    cudaGetSymbolAddress((void**)&halfbase, g_half);
    __half* xh   = halfbase;                          // [N][64]
    __half* g1s1 = halfbase + (size_t)N_MAX * 64;     // [N][128]: g1 | s1 interleaved

    const size_t sm1 = (size_t)(128 + 64) * 72 * 2 * 2;    //  55296 (K=64)
    const size_t sm2 = (size_t)(128 + 64) * 136 * 2 * 2;   // 104448 (K=128)
    cudaFuncSetAttribute(k_gemm<false, true, false, true>,
                         cudaFuncAttributeMaxDynamicSharedMemorySize, (int)sm1);
    cudaFuncSetAttribute(k_gemm<true, true, false, true>,
                         cudaFuncAttributeMaxDynamicSharedMemorySize, (int)sm2);
    cudaFuncSetAttribute(k_gemm<false, false, false, false>,
                         cudaFuncAttributeMaxDynamicSharedMemorySize, (int)sm1);
    cudaFuncSetAttribute(k_gemm<true, false, true, false>,
                         cudaFuncAttributeMaxDynamicSharedMemorySize, (int)sm2);
    cudaFuncSetAttribute(k_proj,
                         cudaFuncAttributeMaxDynamicSharedMemorySize, (int)sm2);

    int nb1k = (n + 1023) / 1024;
    int gb   = (n + 127) / 128;
    int ab   = (n + 7) / 8;       // warp-per-node blocks (256 thr)

    // CSR build + x fp16 conversion
    k_prep<<<(n * 16 + 255) / 256, 256>>>(ei, x, xh, e, n);
    k_count<<<(e + 255) / 256, 256>>>(ei, e, n);
    k_scan1<<<nb1k, 1024>>>(n);
    k_scan23<<<nb1k, 1024>>>(n, nb1k);
    k_scatter<<<(e + 255) / 256, 256>>>(ei, e, n);

    // Layer 1: wide-lane dual aggregation over xh, then the two layer-1 GEMMs
    // (fp16 outputs interleaved into g1s1: g1 at offset 0, s1 at offset 64; stride 128)
    k_agg_dual1<<<ab, 256>>>(xh, B[0], B[1], n);
    k_gemm<false, true, false, true><<<gb, 256, sm1>>>(
        B[0], gcn_w1, nullptr, nullptr, gcn_b1, g1s1, n, 64, 128);
    k_gemm<true, true, false, true><<<gb, 256, sm2>>>(
        B[1], sage_wl1, x, sage_wr1, sage_bl1, g1s1 + 64, n, 64, 128);

    // Layer 2: wide-lane dual aggregation over interleaved g1|s1, then layer-2 GEMMs
    k_agg_dual2<<<ab, 256>>>(g1s1, B[0], B[1], n);
    k_gemm<false, false, false, false><<<gb, 256, sm1>>>(
        B[0], gcn_w2, nullptr, nullptr, gcn_b2, B[4], n, 64, 64);
    k_gemm<true, false, true, false><<<gb, 256, sm2>>>(
        B[1], sage_wl2, g1s1 + 64, sage_wr2, sage_bl2, B[5], n, 128, 64);

    // Fused LayerNorm + concat projection (tensor-core)
    k_proj<<<gb, 256, sm2>>>(B[4], B[5], gln_g, gln_b, sln_g, sln_b,
                             proj_w, proj_b, out, n);
}

// round 15
// speedup vs baseline: 1.0649x; 1.0649x over previous
#include <cuda_runtime.h>
#include <cuda_bf16.h>
#include <cuda_fp16.h>
#include <cstdint>

#define N_MAX 100000
#define E_MAX 1250000

// ---------------- scratch (static device allocations; no runtime alloc) -----
__device__ int    g_is64;
__device__ int    g_deg[N_MAX];
__device__ int    g_incl[N_MAX];
__device__ int    g_rowptr[N_MAX];
__device__ int    g_cursor[N_MAX];
__device__ int    g_bsum[256];
__device__ float  g_dinv[N_MAX];   // rsqrt(indeg+1)  (GCN)
__device__ float  g_cinv[N_MAX];   // 1/max(indeg,1)  (SAGE mean)
__device__ int    g_edge[E_MAX];   // src index, bucketed by dst
__device__ float  g_buf[6][(size_t)N_MAX * 64];
__device__ __half g_half[3][(size_t)N_MAX * 64];   // xh, g1h, s1h

// ---------------- fused: zero degrees + x->fp16 + dtype detection ------------
__global__ void k_prep(const void* __restrict__ ei, const float* __restrict__ x,
                       __half* __restrict__ xh, int e, int n) {
    int i = blockIdx.x * blockDim.x + threadIdx.x;
    if (i < n) g_deg[i] = 0;
    int total = n * 16;   // float4 quads
    if (i < total) {
        float4 v = ((const float4*)x)[i];
        __half2 h0 = __floats2half2_rn(v.x, v.y);
        __half2 h1 = __floats2half2_rn(v.z, v.w);
        ((__half2*)xh)[i * 2]     = h0;
        ((__half2*)xh)[i * 2 + 1] = h1;
    }
    if (blockIdx.x == 0) {
        __shared__ int bad;
        if (threadIdx.x == 0) bad = 0;
        __syncthreads();
        const long long* p = (const long long*)ei;
        int m = e < 2048 ? e : 2048;
        for (int j = threadIdx.x; j < m; j += blockDim.x) {
            long long v = p[j];
            if (v < 0 || v >= (long long)n) bad = 1;
        }
        __syncthreads();
        if (threadIdx.x == 0) g_is64 = bad ? 0 : 1;
    }
}

__device__ __forceinline__ int ld_idx(const void* __restrict__ ei, int is64,
                                      long long pos, int n) {
    long long v = is64 ? ((const long long*)ei)[pos]
                       : (long long)((const int*)ei)[pos];
    int s = (int)v;
    if ((unsigned)s >= (unsigned)n) s = 0;   // trap-safety clamp
    return s;
}

// ---------------- CSR build --------------------------------------------------
__global__ void k_count(const void* __restrict__ ei, int e, int n) {
    int i = blockIdx.x * blockDim.x + threadIdx.x;
    if (i >= e) return;
    int is64 = g_is64;
    int d = ld_idx(ei, is64, (long long)e + i, n);
    atomicAdd(&g_deg[d], 1);
}

__global__ void k_scan1(int n) {  // per-block inclusive scan (1024/block)
    __shared__ int sh[1024];
    int t = threadIdx.x;
    int i = blockIdx.x * 1024 + t;
    int v = (i < n) ? g_deg[i] : 0;
    sh[t] = v;
    __syncthreads();
    for (int off = 1; off < 1024; off <<= 1) {
        int add = (t >= off) ? sh[t - off] : 0;
        __syncthreads();
        sh[t] += add;
        __syncthreads();
    }
    if (i < n) g_incl[i] = sh[t];
    if (t == 1023) g_bsum[blockIdx.x] = sh[1023];
}

// fused scan2+scan3: every block redundantly scans the <=256 block sums in smem
__global__ void k_scan23(int n, int nb) {
    __shared__ int sh[256];
    __shared__ int orig[256];
    int t = threadIdx.x;
    if (t < 256) {
        int v = (t < nb) ? g_bsum[t] : 0;
        sh[t] = v;
        orig[t] = v;
    }
    __syncthreads();
    for (int off = 1; off < 256; off <<= 1) {
        int add = (t < 256 && t >= off) ? sh[t - off] : 0;
        __syncthreads();
        if (t < 256) sh[t] += add;
        __syncthreads();
    }
    int i = blockIdx.x * 1024 + t;
    if (i >= n) return;
    int boff = sh[blockIdx.x] - orig[blockIdx.x];  // exclusive prefix of this block
    int d  = g_deg[i];
    int rp = g_incl[i] - d + boff;
    g_rowptr[i] = rp;
    g_cursor[i] = rp;
    g_dinv[i] = rsqrtf((float)d + 1.0f);
    g_cinv[i] = 1.0f / fmaxf((float)d, 1.0f);
}

__global__ void k_scatter(const void* __restrict__ ei, int e, int n) {
    int i = blockIdx.x * blockDim.x + threadIdx.x;
    if (i >= e) return;
    int is64 = g_is64;
    int s = ld_idx(ei, is64, i, n);
    int d = ld_idx(ei, is64, (long long)e + i, n);
    int pos = atomicAdd(&g_cursor[d], 1);
    g_edge[pos] = s;
}

// ---------------- fused dual aggregations (warp per node, 2 feats/lane) -----
// fp16 feature rows (128 B), fp32 accumulation. Edge loop unrolled x2 with
// independent gathers (MLP 2x, no shfl).
__global__ void k_agg_dual1(const __half* __restrict__ xh,
                            float* __restrict__ outG, float* __restrict__ outM, int n) {
    int gw   = (blockIdx.x * blockDim.x + threadIdx.x) >> 5;
    int lane = threadIdx.x & 31;
    if (gw >= n) return;
    int start = g_rowptr[gw];
    int cnt   = g_deg[gw];
    float wx = 0.f, wy = 0.f, mx = 0.f, my = 0.f;
    int e = 0;
    for (; e + 2 <= cnt; e += 2) {
        int i0 = g_edge[start + e];
        int i1 = g_edge[start + e + 1];
        float d0 = g_dinv[i0], d1 = g_dinv[i1];
        float2 v0 = __half22float2(*(const __half2*)(xh + (size_t)i0 * 64 + lane * 2));
        float2 v1 = __half22float2(*(const __half2*)(xh + (size_t)i1 * 64 + lane * 2));
        wx = fmaf(d0, v0.x, fmaf(d1, v1.x, wx));
        wy = fmaf(d0, v0.y, fmaf(d1, v1.y, wy));
        mx += v0.x + v1.x;
        my += v0.y + v1.y;
    }
    for (; e < cnt; e++) {
        int i0 = g_edge[start + e];
        float d0 = g_dinv[i0];
        float2 v0 = __half22float2(*(const __half2*)(xh + (size_t)i0 * 64 + lane * 2));
        wx = fmaf(d0, v0.x, wx);
        wy = fmaf(d0, v0.y, wy);
        mx += v0.x;
        my += v0.y;
    }
    float dd = g_dinv[gw];
    float ci = g_cinv[gw];
    float2 xv = __half22float2(*(const __half2*)(xh + (size_t)gw * 64 + lane * 2));
    float2 og = make_float2(fmaf(dd, wx, dd * dd * xv.x),
                            fmaf(dd, wy, dd * dd * xv.y));
    float2 om = make_float2(mx * ci, my * ci);
    *(float2*)(outG + (size_t)gw * 64 + lane * 2) = og;
    *(float2*)(outM + (size_t)gw * 64 + lane * 2) = om;
}

__global__ void k_agg_dual2(const __half* __restrict__ g1h, const __half* __restrict__ s1h,
                            float* __restrict__ outG, float* __restrict__ outM, int n) {
    int gw   = (blockIdx.x * blockDim.x + threadIdx.x) >> 5;
    int lane = threadIdx.x & 31;
    if (gw >= n) return;
    int start = g_rowptr[gw];
    int cnt   = g_deg[gw];
    float wx = 0.f, wy = 0.f, mx = 0.f, my = 0.f;
    int e = 0;
    for (; e + 2 <= cnt; e += 2) {
        int i0 = g_edge[start + e];
        int i1 = g_edge[start + e + 1];
        float d0 = g_dinv[i0], d1 = g_dinv[i1];
        float2 a0 = __half22float2(*(const __half2*)(g1h + (size_t)i0 * 64 + lane * 2));
        float2 a1 = __half22float2(*(const __half2*)(g1h + (size_t)i1 * 64 + lane * 2));
        float2 b0 = __half22float2(*(const __half2*)(s1h + (size_t)i0 * 64 + lane * 2));
        float2 b1 = __half22float2(*(const __half2*)(s1h + (size_t)i1 * 64 + lane * 2));
        wx = fmaf(d0, a0.x, fmaf(d1, a1.x, wx));
        wy = fmaf(d0, a0.y, fmaf(d1, a1.y, wy));
        mx += b0.x + b1.x;
        my += b0.y + b1.y;
    }
    for (; e < cnt; e++) {
        int i0 = g_edge[start + e];
        float d0 = g_dinv[i0];
        float2 a0 = __half22float2(*(const __half2*)(g1h + (size_t)i0 * 64 + lane * 2));
        float2 b0 = __half22float2(*(const __half2*)(s1h + (size_t)i0 * 64 + lane * 2));
        wx = fmaf(d0, a0.x, wx);
        wy = fmaf(d0, a0.y, wy);
        mx += b0.x;
        my += b0.y;
    }
    float dd = g_dinv[gw];
    float ci = g_cinv[gw];
    float2 gsv = __half22float2(*(const __half2*)(g1h + (size_t)gw * 64 + lane * 2));
    float2 og = make_float2(fmaf(dd, wx, dd * dd * gsv.x),
                            fmaf(dd, wy, dd * dd * gsv.y));
    float2 om = make_float2(mx * ci, my * ci);
    *(float2*)(outG + (size_t)gw * 64 + lane * 2) = og;
    *(float2*)(outM + (size_t)gw * 64 + lane * 2) = om;
}

// ---------------- tensor-core GEMM via split-bf16 (3-term) -------------------
__device__ __forceinline__ void mma_bf16(float* c,
                                         uint32_t a0, uint32_t a1, uint32_t a2, uint32_t a3,
                                         uint32_t b0, uint32_t b1) {
    asm volatile(
        "mma.sync.aligned.m16n8k16.row.col.f32.bf16.bf16.f32 "
        "{%0,%1,%2,%3}, {%4,%5,%6,%7}, {%8,%9}, {%0,%1,%2,%3};\n"
        : "+f"(c[0]), "+f"(c[1]), "+f"(c[2]), "+f"(c[3])
        : "r"(a0), "r"(a1), "r"(a2), "r"(a3), "r"(b0), "r"(b1));
}

__device__ __forceinline__ void split_pack(float x, float y, uint32_t& hi, uint32_t& lo) {
    __nv_bfloat162 h = __floats2bfloat162_rn(x, y);
    __nv_bfloat162 l = __floats2bfloat162_rn(x - __bfloat162float(h.x),
                                             y - __bfloat162float(h.y));
    hi = *(uint32_t*)&h;
    lo = *(uint32_t*)&l;
}

// Y = act( Xa@Wa [+ Xb@Wb] + bias ).  Xa fp32; Xb fp32 or fp16; Y fp32 or fp16.
template <bool DUAL, bool RELU, bool XB_HALF, bool OUT_HALF>
__global__ void k_gemm(const float* __restrict__ Xa, const float* __restrict__ Wa,
                       const void* __restrict__ Xb, const float* __restrict__ Wb,
                       const float* __restrict__ bias, void* __restrict__ Yv, int n) {
    constexpr int KT  = DUAL ? 128 : 64;
    constexpr int KP  = KT + 8;
    constexpr int KPW = KP / 2;
    extern __shared__ uint32_t smu[];
    uint32_t* Ahi = smu;
    uint32_t* Alo = Ahi + 128 * KPW;
    uint32_t* Bhi = Alo + 128 * KPW;
    uint32_t* Blo = Bhi + 64 * KPW;

    int tid  = threadIdx.x;
    int base = blockIdx.x * 128;

    __nv_bfloat16* BhiH = (__nv_bfloat16*)Bhi;
    __nv_bfloat16* BloH = (__nv_bfloat16*)Blo;
    for (int i = tid; i < KT * 16; i += 256) {
        int k = i >> 4, c = (i & 15) << 2;
        const float* wsrc = (DUAL && k >= 64) ? (Wb + (size_t)(k - 64) * 64 + c)
                                              : (Wa + (size_t)k * 64 + c);
        float4 v = *(const float4*)wsrc;
        float vv[4] = {v.x, v.y, v.z, v.w};
#pragma unroll
        for (int j = 0; j < 4; j++) {
            __nv_bfloat16 h = __float2bfloat16_rn(vv[j]);
            BhiH[(c + j) * KP + k] = h;
            BloH[(c + j) * KP + k] = __float2bfloat16_rn(vv[j] - __bfloat162float(h));
        }
    }
    constexpr int KQ4 = KT / 4;
    for (int i = tid; i < 128 * KQ4; i += 256) {
        int r  = i / KQ4;
        int kq = i % KQ4;
        int row = base + r;
        float4 v = make_float4(0.f, 0.f, 0.f, 0.f);
        if (row < n) {
            int k = kq * 4;
            if (DUAL && k >= 64) {
                if (XB_HALF) {
                    const __half* xb = (const __half*)Xb + (size_t)row * 64 + (k - 64);
                    float2 fa = __half22float2(*(const __half2*)xb);
                    float2 fb = __half22float2(*(const __half2*)(xb + 2));
                    v = make_float4(fa.x, fa.y, fb.x, fb.y);
                } else {
                    v = *(const float4*)((const float*)Xb + (size_t)row * 64 + (k - 64));
                }
            } else {
                v = *(const float4*)(Xa + (size_t)row * 64 + k);
            }
        }
        uint32_t h0, l0, h1, l1;
        split_pack(v.x, v.y, h0, l0);
        split_pack(v.z, v.w, h1, l1);
        int wo = r * KPW + kq * 2;
        Ahi[wo]     = h0;
        Ahi[wo + 1] = h1;
        Alo[wo]     = l0;
        Alo[wo + 1] = l1;
    }
    __syncthreads();

    int warp  = tid >> 5;
    int lane  = tid & 31;
    int tq    = lane >> 2;
    int tc    = lane & 3;
    int rbase = warp * 16;

    float acc[8][4];
#pragma unroll
    for (int nt = 0; nt < 8; nt++)
#pragma unroll
        for (int c = 0; c < 4; c++) acc[nt][c] = 0.f;

#pragma unroll
    for (int kk = 0; kk < KT / 16; kk++) {
        int colw = kk * 8 + tc;
        int ra = (rbase + tq) * KPW + colw;
        int rb = ra + 8 * KPW;
        uint32_t ah0 = Ahi[ra], ah1 = Ahi[rb], ah2 = Ahi[ra + 4], ah3 = Ahi[rb + 4];
        uint32_t al0 = Alo[ra], al1 = Alo[rb], al2 = Alo[ra + 4], al3 = Alo[rb + 4];
#pragma unroll
        for (int nt = 0; nt < 8; nt++) {
            int nb = (nt * 8 + tq) * KPW + colw;
            uint32_t bh0 = Bhi[nb], bh1 = Bhi[nb + 4];
            uint32_t bl0 = Blo[nb], bl1 = Blo[nb + 4];
            mma_bf16(acc[nt], ah0, ah1, ah2, ah3, bh0, bh1);
            mma_bf16(acc[nt], ah0, ah1, ah2, ah3, bl0, bl1);
            mma_bf16(acc[nt], al0, al1, al2, al3, bh0, bh1);
        }
    }

    int r0 = base + rbase + tq;
    int r1 = r0 + 8;
#pragma unroll
    for (int nt = 0; nt < 8; nt++) {
        int col = nt * 8 + 2 * tc;
        float2 bv = *(const float2*)&bias[col];
        float2 o0 = make_float2(acc[nt][0] + bv.x, acc[nt][1] + bv.y);
        float2 o1 = make_float2(acc[nt][2] + bv.x, acc[nt][3] + bv.y);
        if (RELU) {
            o0.x = fmaxf(o0.x, 0.f); o0.y = fmaxf(o0.y, 0.f);
            o1.x = fmaxf(o1.x, 0.f); o1.y = fmaxf(o1.y, 0.f);
        }
        if (OUT_HALF) {
            __half* Y = (__half*)Yv;
            if (r0 < n) *(__half2*)&Y[(size_t)r0 * 64 + col] = __floats2half2_rn(o0.x, o0.y);
            if (r1 < n) *(__half2*)&Y[(size_t)r1 * 64 + col] = __floats2half2_rn(o1.x, o1.y);
        } else {
            float* Y = (float*)Yv;
            if (r0 < n) *(float2*)&Y[(size_t)r0 * 64 + col] = o0;
            if (r1 < n) *(float2*)&Y[(size_t)r1 * 64 + col] = o1;
        }
    }
}

// ---------------- projection GEMM with fused per-branch LayerNorm -----------
__global__ void k_proj(const float* __restrict__ G, const float* __restrict__ S,
                       const float* __restrict__ gg, const float* __restrict__ gb,
                       const float* __restrict__ sg, const float* __restrict__ sb,
                       const float* __restrict__ W, const float* __restrict__ bias,
                       float* __restrict__ Y, int n) {
    constexpr int KT = 128, KP = 136, KPW = 68;
    extern __shared__ uint32_t smu[];
    uint32_t* Ahi = smu;
    uint32_t* Alo = Ahi + 128 * KPW;
    uint32_t* Bhi = Alo + 128 * KPW;
    uint32_t* Blo = Bhi + 64 * KPW;

    int tid  = threadIdx.x;
    int warp = tid >> 5;
    int lane = tid & 31;
    int base = blockIdx.x * 128;

    __nv_bfloat16* BhiH = (__nv_bfloat16*)Bhi;
    __nv_bfloat16* BloH = (__nv_bfloat16*)Blo;
    for (int i = tid; i < 128 * 16; i += 256) {
        int k = i >> 4, c = (i & 15) << 2;
        float4 v = *(const float4*)(W + (size_t)k * 64 + c);
        float vv[4] = {v.x, v.y, v.z, v.w};
#pragma unroll
        for (int j = 0; j < 4; j++) {
            __nv_bfloat16 h = __float2bfloat16_rn(vv[j]);
            BhiH[(c + j) * KP + k] = h;
            BloH[(c + j) * KP + k] = __float2bfloat16_rn(vv[j] - __bfloat162float(h));
        }
    }

    float2 ggv = *(const float2*)&gg[lane * 2];
    float2 gbv = *(const float2*)&gb[lane * 2];
    float2 sgv = *(const float2*)&sg[lane * 2];
    float2 sbv = *(const float2*)&sb[lane * 2];
    for (int it = 0; it < 16; it++) {
        int r   = warp * 16 + it;
        int row = base + r;
        float2 gv = make_float2(0.f, 0.f), sv = make_float2(0.f, 0.f);
        if (row < n) {
            gv = *(const float2*)(G + (size_t)row * 64 + lane * 2);
            sv = *(const float2*)(S + (size_t)row * 64 + lane * 2);
        }
        float sgm = gv.x + gv.y, qg = gv.x * gv.x + gv.y * gv.y;
        float ssm = sv.x + sv.y, qs = sv.x * sv.x + sv.y * sv.y;
#pragma unroll
        for (int o = 16; o > 0; o >>= 1) {
            sgm += __shfl_xor_sync(0xffffffffu, sgm, o);
            qg  += __shfl_xor_sync(0xffffffffu, qg, o);
            ssm += __shfl_xor_sync(0xffffffffu, ssm, o);
            qs  += __shfl_xor_sync(0xffffffffu, qs, o);
        }
        float mug  = sgm * (1.0f / 64.0f);
        float varg = fmaxf(qg * (1.0f / 64.0f) - mug * mug, 0.f);
        float rg   = rsqrtf(varg + 1e-5f);
        float mus  = ssm * (1.0f / 64.0f);
        float vars = fmaxf(qs * (1.0f / 64.0f) - mus * mus, 0.f);
        float rs   = rsqrtf(vars + 1e-5f);
        float ogx = (gv.x - mug) * rg * ggv.x + gbv.x;
        float ogy = (gv.y - mug) * rg * ggv.y + gbv.y;
        float osx = (sv.x - mus) * rs * sgv.x + sbv.x;
        float osy = (sv.y - mus) * rs * sgv.y + sbv.y;
        uint32_t h, l;
        split_pack(ogx, ogy, h, l);
        Ahi[r * KPW + lane] = h;
        Alo[r * KPW + lane] = l;
        split_pack(osx, osy, h, l);
        Ahi[r * KPW + 32 + lane] = h;
        Alo[r * KPW + 32 + lane] = l;
    }
    __syncthreads();

    int tq    = lane >> 2;
    int tc    = lane & 3;
    int rbase = warp * 16;

    float acc[8][4];
#pragma unroll
    for (int nt = 0; nt < 8; nt++)
#pragma unroll
        for (int c = 0; c < 4; c++) acc[nt][c] = 0.f;

#pragma unroll
    for (int kk = 0; kk < KT / 16; kk++) {
        int colw = kk * 8 + tc;
        int ra = (rbase + tq) * KPW + colw;
        int rb = ra + 8 * KPW;
        uint32_t ah0 = Ahi[ra], ah1 = Ahi[rb], ah2 = Ahi[ra + 4], ah3 = Ahi[rb + 4];
        uint32_t al0 = Alo[ra], al1 = Alo[rb], al2 = Alo[ra + 4], al3 = Alo[rb + 4];
#pragma unroll
        for (int nt = 0; nt < 8; nt++) {
            int nb = (nt * 8 + tq) * KPW + colw;
            uint32_t bh0 = Bhi[nb], bh1 = Bhi[nb + 4];
            uint32_t bl0 = Blo[nb], bl1 = Blo[nb + 4];
            mma_bf16(acc[nt], ah0, ah1, ah2, ah3, bh0, bh1);
            mma_bf16(acc[nt], ah0, ah1, ah2, ah3, bl0, bl1);
            mma_bf16(acc[nt], al0, al1, al2, al3, bh0, bh1);
        }
    }

    int r0 = base + rbase + tq;
    int r1 = r0 + 8;
#pragma unroll
    for (int nt = 0; nt < 8; nt++) {
        int col = nt * 8 + 2 * tc;
        float2 bv = *(const float2*)&bias[col];
        float2 o0 = make_float2(acc[nt][0] + bv.x, acc[nt][1] + bv.y);
        float2 o1 = make_float2(acc[nt][2] + bv.x, acc[nt][3] + bv.y);
        if (r0 < n) *(float2*)&Y[(size_t)r0 * 64 + col] = o0;
        if (r1 < n) *(float2*)&Y[(size_t)r1 * 64 + col] = o1;
    }
}

// ---------------- launcher ---------------------------------------------------
extern "C" void kernel_launch(void* const* d_in, const int* in_sizes, int n_in,
                              void* d_out, int out_size) {
    const float* x        = (const float*)d_in[0];
    const void*  ei       = d_in[1];                 // int64 or int32; auto-detected
    const float* gcn_w1   = (const float*)d_in[2];
    const float* gcn_b1   = (const float*)d_in[3];
    const float* gcn_w2   = (const float*)d_in[4];
    const float* gcn_b2   = (const float*)d_in[5];
    const float* sage_wl1 = (const float*)d_in[6];
    const float* sage_bl1 = (const float*)d_in[7];
    const float* sage_wr1 = (const float*)d_in[8];
    const float* sage_wl2 = (const float*)d_in[9];
    const float* sage_bl2 = (const float*)d_in[10];
    const float* sage_wr2 = (const float*)d_in[11];
    const float* gln_g    = (const float*)d_in[12];
    const float* gln_b    = (const float*)d_in[13];
    const float* sln_g    = (const float*)d_in[14];
    const float* sln_b    = (const float*)d_in[15];
    const float* proj_w   = (const float*)d_in[16];
    const float* proj_b   = (const float*)d_in[17];
    float*       out      = (float*)d_out;

    int n = in_sizes[0] / 64;
    int e = in_sizes[1] / 2;

    float* bufbase = nullptr;
    cudaGetSymbolAddress((void**)&bufbase, g_buf);
    float* B[6];
    for (int i = 0; i < 6; i++) B[i] = bufbase + (size_t)i * N_MAX * 64;
    __half* halfbase = nullptr;
    cudaGetSymbolAddress((void**)&halfbase, g_half);
    __half* xh  = halfbase;
    __half* g1h = halfbase + (size_t)N_MAX * 64;
    __half* s1h = halfbase + (size_t)2 * N_MAX * 64;

    const size_t sm1 = (size_t)(128 + 64) * 72 * 2 * 2;    //  55296 (K=64)
    const size_t sm2 = (size_t)(128 + 64) * 136 * 2 * 2;   // 104448 (K=128)
    cudaFuncSetAttribute(k_gemm<false, true, false, true>,
                         cudaFuncAttributeMaxDynamicSharedMemorySize, (int)sm1);
    cudaFuncSetAttribute(k_gemm<true, true, false, true>,
                         cudaFuncAttributeMaxDynamicSharedMemorySize, (int)sm2);
    cudaFuncSetAttribute(k_gemm<false, false, false, false>,
                         cudaFuncAttributeMaxDynamicSharedMemorySize, (int)sm1);
    cudaFuncSetAttribute(k_gemm<true, false, true, false>,
                         cudaFuncAttributeMaxDynamicSharedMemorySize, (int)sm2);
    cudaFuncSetAttribute(k_proj,
                         cudaFuncAttributeMaxDynamicSharedMemorySize, (int)sm2);

    int nb1k = (n + 1023) / 1024;
    int gb   = (n + 127) / 128;
    int ab   = (n + 7) / 8;       // warp-per-node blocks (256 thr)

    // CSR build + x fp16 conversion
    k_prep<<<(n * 16 + 255) / 256, 256>>>(ei, x, xh, e, n);
    k_count<<<(e + 255) / 256, 256>>>(ei, e, n);
    k_scan1<<<nb1k, 1024>>>(n);
    k_scan23<<<nb1k, 1024>>>(n, nb1k);
    k_scatter<<<(e + 255) / 256, 256>>>(ei, e, n);

    // Layer 1: fused dual aggregation over xh, then the two layer-1 GEMMs (fp16 out)
    k_agg_dual1<<<ab, 256>>>(xh, B[0], B[1], n);                      // B0=GCN-agg, B1=mean
    k_gemm<false, true, false, true><<<gb, 256, sm1>>>(B[0], gcn_w1, nullptr, nullptr, gcn_b1, g1h, n);
    k_gemm<true,  true, false, true><<<gb, 256, sm2>>>(B[1], sage_wl1, x, sage_wr1, sage_bl1, s1h, n);

    // Layer 2: fused dual aggregation over (g1h, s1h), then the two layer-2 GEMMs
    k_agg_dual2<<<ab, 256>>>(g1h, s1h, B[0], B[1], n);                // B0=GCN-agg, B1=mean
    k_gemm<false, false, false, false><<<gb, 256, sm1>>>(B[0], gcn_w2, nullptr, nullptr, gcn_b2, B[4], n);
    k_gemm<true,  false, true,  false><<<gb, 256, sm2>>>(B[1], sage_wl2, s1h, sage_wr2, sage_bl2, B[5], n);

    // Fused LayerNorm + concat projection (tensor-core)
    k_proj<<<gb, 256, sm2>>>(B[4], B[5], gln_g, gln_b, sln_g, sln_b,
                             proj_w, proj_b, out, n);
}

// round 16
// speedup vs baseline: 1.0972x; 1.0303x over previous
#include <cuda_runtime.h>
#include <cuda_bf16.h>
#include <cuda_fp16.h>
#include <cstdint>

#define N_MAX 100000
#define E_MAX 1250000

// ---------------- scratch (static device allocations; no runtime alloc) -----
__device__ int    g_is64;
__device__ int    g_deg[N_MAX];
__device__ int    g_incl[N_MAX];
__device__ int    g_rowptr[N_MAX];
__device__ int    g_cursor[N_MAX];
__device__ int    g_bsum[256];
__device__ float  g_dinv[N_MAX];   // rsqrt(indeg+1)  (GCN)
__device__ float  g_cinv[N_MAX];   // 1/max(indeg,1)  (SAGE mean)
__device__ int    g_edge[E_MAX];   // src index, bucketed by dst
__device__ float  g_buf[6][(size_t)N_MAX * 64];
__device__ __half g_half[3][(size_t)N_MAX * 64];   // xh, g1h, s1h

// ---------------- fused: zero degrees + x->fp16 + dtype detection ------------
__global__ void k_prep(const void* __restrict__ ei, const float* __restrict__ x,
                       __half* __restrict__ xh, int e, int n) {
    int i = blockIdx.x * blockDim.x + threadIdx.x;
    if (i < n) g_deg[i] = 0;
    int total = n * 16;   // float4 quads
    if (i < total) {
        float4 v = ((const float4*)x)[i];
        __half2 h0 = __floats2half2_rn(v.x, v.y);
        __half2 h1 = __floats2half2_rn(v.z, v.w);
        ((__half2*)xh)[i * 2]     = h0;
        ((__half2*)xh)[i * 2 + 1] = h1;
    }
    if (blockIdx.x == 0) {
        __shared__ int bad;
        if (threadIdx.x == 0) bad = 0;
        __syncthreads();
        const long long* p = (const long long*)ei;
        int m = e < 2048 ? e : 2048;
        for (int j = threadIdx.x; j < m; j += blockDim.x) {
            long long v = p[j];
            if (v < 0 || v >= (long long)n) bad = 1;
        }
        __syncthreads();
        if (threadIdx.x == 0) g_is64 = bad ? 0 : 1;
    }
}

__device__ __forceinline__ int ld_idx(const void* __restrict__ ei, int is64,
                                      long long pos, int n) {
    long long v = is64 ? ((const long long*)ei)[pos]
                       : (long long)((const int*)ei)[pos];
    int s = (int)v;
    if ((unsigned)s >= (unsigned)n) s = 0;   // trap-safety clamp
    return s;
}

// ---------------- CSR build --------------------------------------------------
__global__ void k_count(const void* __restrict__ ei, int e, int n) {
    int i = blockIdx.x * blockDim.x + threadIdx.x;
    if (i >= e) return;
    int is64 = g_is64;
    int d = ld_idx(ei, is64, (long long)e + i, n);
    atomicAdd(&g_deg[d], 1);
}

__global__ void k_scan1(int n) {  // per-block inclusive scan (1024/block)
    __shared__ int sh[1024];
    int t = threadIdx.x;
    int i = blockIdx.x * 1024 + t;
    int v = (i < n) ? g_deg[i] : 0;
    sh[t] = v;
    __syncthreads();
    for (int off = 1; off < 1024; off <<= 1) {
        int add = (t >= off) ? sh[t - off] : 0;
        __syncthreads();
        sh[t] += add;
        __syncthreads();
    }
    if (i < n) g_incl[i] = sh[t];
    if (t == 1023) g_bsum[blockIdx.x] = sh[1023];
}

// fused scan2+scan3: every block redundantly scans the <=256 block sums in smem
__global__ void k_scan23(int n, int nb) {
    __shared__ int sh[256];
    __shared__ int orig[256];
    int t = threadIdx.x;
    if (t < 256) {
        int v = (t < nb) ? g_bsum[t] : 0;
        sh[t] = v;
        orig[t] = v;
    }
    __syncthreads();
    for (int off = 1; off < 256; off <<= 1) {
        int add = (t < 256 && t >= off) ? sh[t - off] : 0;
        __syncthreads();
        if (t < 256) sh[t] += add;
        __syncthreads();
    }
    int i = blockIdx.x * 1024 + t;
    if (i >= n) return;
    int boff = sh[blockIdx.x] - orig[blockIdx.x];  // exclusive prefix of this block
    int d  = g_deg[i];
    int rp = g_incl[i] - d + boff;
    g_rowptr[i] = rp;
    g_cursor[i] = rp;
    g_dinv[i] = rsqrtf((float)d + 1.0f);
    g_cinv[i] = 1.0f / fmaxf((float)d, 1.0f);
}

__global__ void k_scatter(const void* __restrict__ ei, int e, int n) {
    int i = blockIdx.x * blockDim.x + threadIdx.x;
    if (i >= e) return;
    int is64 = g_is64;
    int s = ld_idx(ei, is64, i, n);
    int d = ld_idx(ei, is64, (long long)e + i, n);
    int pos = atomicAdd(&g_cursor[d], 1);
    g_edge[pos] = s;
}

// ---------------- fused dual aggregations (warp per node, 2 feats/lane) -----
// R13 form (best measured): software-pipelined prefetch, one gather per iter.
__global__ void k_agg_dual1(const __half* __restrict__ xh,
                            float* __restrict__ outG, float* __restrict__ outM, int n) {
    int gw   = (blockIdx.x * blockDim.x + threadIdx.x) >> 5;
    int lane = threadIdx.x & 31;
    if (gw >= n) return;
    int start = g_rowptr[gw];
    int cnt   = g_deg[gw];
    float wx = 0.f, wy = 0.f, mx = 0.f, my = 0.f;
    int src = (cnt > 0) ? g_edge[start] : 0;
    for (int e = 0; e < cnt; e++) {
        int cur = src;
        if (e + 1 < cnt) src = g_edge[start + e + 1];
        float ds = g_dinv[cur];
        float2 v = __half22float2(*(const __half2*)(xh + (size_t)cur * 64 + lane * 2));
        wx = fmaf(ds, v.x, wx);
        wy = fmaf(ds, v.y, wy);
        mx += v.x;
        my += v.y;
    }
    float dd = g_dinv[gw];
    float ci = g_cinv[gw];
    float2 xv = __half22float2(*(const __half2*)(xh + (size_t)gw * 64 + lane * 2));
    float2 og = make_float2(fmaf(dd, wx, dd * dd * xv.x),
                            fmaf(dd, wy, dd * dd * xv.y));
    float2 om = make_float2(mx * ci, my * ci);
    *(float2*)(outG + (size_t)gw * 64 + lane * 2) = og;
    *(float2*)(outM + (size_t)gw * 64 + lane * 2) = om;
}

__global__ void k_agg_dual2(const __half* __restrict__ g1h, const __half* __restrict__ s1h,
                            float* __restrict__ outG, float* __restrict__ outM, int n) {
    int gw   = (blockIdx.x * blockDim.x + threadIdx.x) >> 5;
    int lane = threadIdx.x & 31;
    if (gw >= n) return;
    int start = g_rowptr[gw];
    int cnt   = g_deg[gw];
    float wx = 0.f, wy = 0.f, mx = 0.f, my = 0.f;
    int src = (cnt > 0) ? g_edge[start] : 0;
    for (int e = 0; e < cnt; e++) {
        int cur = src;
        if (e + 1 < cnt) src = g_edge[start + e + 1];
        float ds = g_dinv[cur];
        float2 gv = __half22float2(*(const __half2*)(g1h + (size_t)cur * 64 + lane * 2));
        float2 sv = __half22float2(*(const __half2*)(s1h + (size_t)cur * 64 + lane * 2));
        wx = fmaf(ds, gv.x, wx);
        wy = fmaf(ds, gv.y, wy);
        mx += sv.x;
        my += sv.y;
    }
    float dd = g_dinv[gw];
    float ci = g_cinv[gw];
    float2 gsv = __half22float2(*(const __half2*)(g1h + (size_t)gw * 64 + lane * 2));
    float2 og = make_float2(fmaf(dd, wx, dd * dd * gsv.x),
                            fmaf(dd, wy, dd * dd * gsv.y));
    float2 om = make_float2(mx * ci, my * ci);
    *(float2*)(outG + (size_t)gw * 64 + lane * 2) = og;
    *(float2*)(outM + (size_t)gw * 64 + lane * 2) = om;
}

// ---------------- tensor-core GEMM via split-bf16 (3-term) -------------------
__device__ __forceinline__ void mma_bf16(float* c,
                                         uint32_t a0, uint32_t a1, uint32_t a2, uint32_t a3,
                                         uint32_t b0, uint32_t b1) {
    asm volatile(
        "mma.sync.aligned.m16n8k16.row.col.f32.bf16.bf16.f32 "
        "{%0,%1,%2,%3}, {%4,%5,%6,%7}, {%8,%9}, {%0,%1,%2,%3};\n"
        : "+f"(c[0]), "+f"(c[1]), "+f"(c[2]), "+f"(c[3])
        : "r"(a0), "r"(a1), "r"(a2), "r"(a3), "r"(b0), "r"(b1));
}

__device__ __forceinline__ void split_pack(float x, float y, uint32_t& hi, uint32_t& lo) {
    __nv_bfloat162 h = __floats2bfloat162_rn(x, y);
    __nv_bfloat162 l = __floats2bfloat162_rn(x - __bfloat162float(h.x),
                                             y - __bfloat162float(h.y));
    hi = *(uint32_t*)&h;
    lo = *(uint32_t*)&l;
}

// Body: Y = act( Xa@Wa [+ Xb@Wb] + bias ).  Xa fp32; Xb fp32/fp16; Y fp32/fp16.
template <bool DUAL, bool RELU, bool XB_HALF, bool OUT_HALF>
__device__ __forceinline__ void gemm_body(
        const float* __restrict__ Xa, const float* __restrict__ Wa,
        const void* __restrict__ Xb, const float* __restrict__ Wb,
        const float* __restrict__ bias, void* __restrict__ Yv, int n) {
    constexpr int KT  = DUAL ? 128 : 64;
    constexpr int KP  = KT + 8;
    constexpr int KPW = KP / 2;
    extern __shared__ uint32_t smu[];
    uint32_t* Ahi = smu;
    uint32_t* Alo = Ahi + 128 * KPW;
    uint32_t* Bhi = Alo + 128 * KPW;
    uint32_t* Blo = Bhi + 64 * KPW;

    int tid  = threadIdx.x;
    int base = blockIdx.x * 128;

    __nv_bfloat16* BhiH = (__nv_bfloat16*)Bhi;
    __nv_bfloat16* BloH = (__nv_bfloat16*)Blo;
    for (int i = tid; i < KT * 16; i += 256) {
        int k = i >> 4, c = (i & 15) << 2;
        const float* wsrc = (DUAL && k >= 64) ? (Wb + (size_t)(k - 64) * 64 + c)
                                              : (Wa + (size_t)k * 64 + c);
        float4 v = *(const float4*)wsrc;
        float vv[4] = {v.x, v.y, v.z, v.w};
#pragma unroll
        for (int j = 0; j < 4; j++) {
            __nv_bfloat16 h = __float2bfloat16_rn(vv[j]);
            BhiH[(c + j) * KP + k] = h;
            BloH[(c + j) * KP + k] = __float2bfloat16_rn(vv[j] - __bfloat162float(h));
        }
    }
    constexpr int KQ4 = KT / 4;
    for (int i = tid; i < 128 * KQ4; i += 256) {
        int r  = i / KQ4;
        int kq = i % KQ4;
        int row = base + r;
        float4 v = make_float4(0.f, 0.f, 0.f, 0.f);
        if (row < n) {
            int k = kq * 4;
            if (DUAL && k >= 64) {
                if (XB_HALF) {
                    const __half* xb = (const __half*)Xb + (size_t)row * 64 + (k - 64);
                    float2 fa = __half22float2(*(const __half2*)xb);
                    float2 fb = __half22float2(*(const __half2*)(xb + 2));
                    v = make_float4(fa.x, fa.y, fb.x, fb.y);
                } else {
                    v = *(const float4*)((const float*)Xb + (size_t)row * 64 + (k - 64));
                }
            } else {
                v = *(const float4*)(Xa + (size_t)row * 64 + k);
            }
        }
        uint32_t h0, l0, h1, l1;
        split_pack(v.x, v.y, h0, l0);
        split_pack(v.z, v.w, h1, l1);
        int wo = r * KPW + kq * 2;
        Ahi[wo]     = h0;
        Ahi[wo + 1] = h1;
        Alo[wo]     = l0;
        Alo[wo + 1] = l1;
    }
    __syncthreads();

    int warp  = tid >> 5;
    int lane  = tid & 31;
    int tq    = lane >> 2;
    int tc    = lane & 3;
    int rbase = warp * 16;

    float acc[8][4];
#pragma unroll
    for (int nt = 0; nt < 8; nt++)
#pragma unroll
        for (int c = 0; c < 4; c++) acc[nt][c] = 0.f;

#pragma unroll
    for (int kk = 0; kk < KT / 16; kk++) {
        int colw = kk * 8 + tc;
        int ra = (rbase + tq) * KPW + colw;
        int rb = ra + 8 * KPW;
        uint32_t ah0 = Ahi[ra], ah1 = Ahi[rb], ah2 = Ahi[ra + 4], ah3 = Ahi[rb + 4];
        uint32_t al0 = Alo[ra], al1 = Alo[rb], al2 = Alo[ra + 4], al3 = Alo[rb + 4];
#pragma unroll
        for (int nt = 0; nt < 8; nt++) {
            int nb = (nt * 8 + tq) * KPW + colw;
            uint32_t bh0 = Bhi[nb], bh1 = Bhi[nb + 4];
            uint32_t bl0 = Blo[nb], bl1 = Blo[nb + 4];
            mma_bf16(acc[nt], ah0, ah1, ah2, ah3, bh0, bh1);
            mma_bf16(acc[nt], ah0, ah1, ah2, ah3, bl0, bl1);
            mma_bf16(acc[nt], al0, al1, al2, al3, bh0, bh1);
        }
    }

    int r0 = base + rbase + tq;
    int r1 = r0 + 8;
#pragma unroll
    for (int nt = 0; nt < 8; nt++) {
        int col = nt * 8 + 2 * tc;
        float2 bv = *(const float2*)&bias[col];
        float2 o0 = make_float2(acc[nt][0] + bv.x, acc[nt][1] + bv.y);
        float2 o1 = make_float2(acc[nt][2] + bv.x, acc[nt][3] + bv.y);
        if (RELU) {
            o0.x = fmaxf(o0.x, 0.f); o0.y = fmaxf(o0.y, 0.f);
            o1.x = fmaxf(o1.x, 0.f); o1.y = fmaxf(o1.y, 0.f);
        }
        if (OUT_HALF) {
            __half* Y = (__half*)Yv;
            if (r0 < n) *(__half2*)&Y[(size_t)r0 * 64 + col] = __floats2half2_rn(o0.x, o0.y);
            if (r1 < n) *(__half2*)&Y[(size_t)r1 * 64 + col] = __floats2half2_rn(o1.x, o1.y);
        } else {
            float* Y = (float*)Yv;
            if (r0 < n) *(float2*)&Y[(size_t)r0 * 64 + col] = o0;
            if (r1 < n) *(float2*)&Y[(size_t)r1 * 64 + col] = o1;
        }
    }
}

// Merged per-layer GEMM pair: blockIdx.y==0 -> GCN (K=64); ==1 -> SAGE dual (K=128).
// L1: RELU + fp16 outputs + fp32 Xb.  L2: no RELU, fp32 outputs, fp16 Xb.
template <bool L1>
__global__ void __launch_bounds__(256)
k_gemm_pair(const float* __restrict__ Xg, const float* __restrict__ Wg,
            const float* __restrict__ bg, void* __restrict__ Yg,
            const float* __restrict__ Xs, const float* __restrict__ Wsl,
            const void* __restrict__ Xb, const float* __restrict__ Wsr,
            const float* __restrict__ bs, void* __restrict__ Ys, int n) {
    if (blockIdx.y == 0) {
        gemm_body<false, L1, false, L1>(Xg, Wg, nullptr, nullptr, bg, Yg, n);
    } else {
        gemm_body<true, L1, !L1, L1>(Xs, Wsl, Xb, Wsr, bs, Ys, n);
    }
}

// ---------------- projection GEMM with fused per-branch LayerNorm -----------
__global__ void k_proj(const float* __restrict__ G, const float* __restrict__ S,
                       const float* __restrict__ gg, const float* __restrict__ gb,
                       const float* __restrict__ sg, const float* __restrict__ sb,
                       const float* __restrict__ W, const float* __restrict__ bias,
                       float* __restrict__ Y, int n) {
    constexpr int KT = 128, KP = 136, KPW = 68;
    extern __shared__ uint32_t smu[];
    uint32_t* Ahi = smu;
    uint32_t* Alo = Ahi + 128 * KPW;
    uint32_t* Bhi = Alo + 128 * KPW;
    uint32_t* Blo = Bhi + 64 * KPW;

    int tid  = threadIdx.x;
    int warp = tid >> 5;
    int lane = tid & 31;
    int base = blockIdx.x * 128;

    __nv_bfloat16* BhiH = (__nv_bfloat16*)Bhi;
    __nv_bfloat16* BloH = (__nv_bfloat16*)Blo;
    for (int i = tid; i < 128 * 16; i += 256) {
        int k = i >> 4, c = (i & 15) << 2;
        float4 v = *(const float4*)(W + (size_t)k * 64 + c);
        float vv[4] = {v.x, v.y, v.z, v.w};
#pragma unroll
        for (int j = 0; j < 4; j++) {
            __nv_bfloat16 h = __float2bfloat16_rn(vv[j]);
            BhiH[(c + j) * KP + k] = h;
            BloH[(c + j) * KP + k] = __float2bfloat16_rn(vv[j] - __bfloat162float(h));
        }
    }

    float2 ggv = *(const float2*)&gg[lane * 2];
    float2 gbv = *(const float2*)&gb[lane * 2];
    float2 sgv = *(const float2*)&sg[lane * 2];
    float2 sbv = *(const float2*)&sb[lane * 2];
    for (int it = 0; it < 16; it++) {
        int r   = warp * 16 + it;
        int row = base + r;
        float2 gv = make_float2(0.f, 0.f), sv = make_float2(0.f, 0.f);
        if (row < n) {
            gv = *(const float2*)(G + (size_t)row * 64 + lane * 2);
            sv = *(const float2*)(S + (size_t)row * 64 + lane * 2);
        }
        float sgm = gv.x + gv.y, qg = gv.x * gv.x + gv.y * gv.y;
        float ssm = sv.x + sv.y, qs = sv.x * sv.x + sv.y * sv.y;
#pragma unroll
        for (int o = 16; o > 0; o >>= 1) {
            sgm += __shfl_xor_sync(0xffffffffu, sgm, o);
            qg  += __shfl_xor_sync(0xffffffffu, qg, o);
            ssm += __shfl_xor_sync(0xffffffffu, ssm, o);
            qs  += __shfl_xor_sync(0xffffffffu, qs, o);
        }
        float mug  = sgm * (1.0f / 64.0f);
        float varg = fmaxf(qg * (1.0f / 64.0f) - mug * mug, 0.f);
        float rg   = rsqrtf(varg + 1e-5f);
        float mus  = ssm * (1.0f / 64.0f);
        float vars = fmaxf(qs * (1.0f / 64.0f) - mus * mus, 0.f);
        float rs   = rsqrtf(vars + 1e-5f);
        float ogx = (gv.x - mug) * rg * ggv.x + gbv.x;
        float ogy = (gv.y - mug) * rg * ggv.y + gbv.y;
        float osx = (sv.x - mus) * rs * sgv.x + sbv.x;
        float osy = (sv.y - mus) * rs * sgv.y + sbv.y;
        uint32_t h, l;
        split_pack(ogx, ogy, h, l);
        Ahi[r * KPW + lane] = h;
        Alo[r * KPW + lane] = l;
        split_pack(osx, osy, h, l);
        Ahi[r * KPW + 32 + lane] = h;
        Alo[r * KPW + 32 + lane] = l;
    }
    __syncthreads();

    int tq    = lane >> 2;
    int tc    = lane & 3;
    int rbase = warp * 16;

    float acc[8][4];
#pragma unroll
    for (int nt = 0; nt < 8; nt++)
#pragma unroll
        for (int c = 0; c < 4; c++) acc[nt][c] = 0.f;

#pragma unroll
    for (int kk = 0; kk < KT / 16; kk++) {
        int colw = kk * 8 + tc;
        int ra = (rbase + tq) * KPW + colw;
        int rb = ra + 8 * KPW;
        uint32_t ah0 = Ahi[ra], ah1 = Ahi[rb], ah2 = Ahi[ra + 4], ah3 = Ahi[rb + 4];
        uint32_t al0 = Alo[ra], al1 = Alo[rb], al2 = Alo[ra + 4], al3 = Alo[rb + 4];
#pragma unroll
        for (int nt = 0; nt < 8; nt++) {
            int nb = (nt * 8 + tq) * KPW + colw;
            uint32_t bh0 = Bhi[nb], bh1 = Bhi[nb + 4];
            uint32_t bl0 = Blo[nb], bl1 = Blo[nb + 4];
            mma_bf16(acc[nt], ah0, ah1, ah2, ah3, bh0, bh1);
            mma_bf16(acc[nt], ah0, ah1, ah2, ah3, bl0, bl1);
            mma_bf16(acc[nt], al0, al1, al2, al3, bh0, bh1);
        }
    }

    int r0 = base + rbase + tq;
    int r1 = r0 + 8;
#pragma unroll
    for (int nt = 0; nt < 8; nt++) {
        int col = nt * 8 + 2 * tc;
        float2 bv = *(const float2*)&bias[col];
        float2 o0 = make_float2(acc[nt][0] + bv.x, acc[nt][1] + bv.y);
        float2 o1 = make_float2(acc[nt][2] + bv.x, acc[nt][3] + bv.y);
        if (r0 < n) *(float2*)&Y[(size_t)r0 * 64 + col] = o0;
        if (r1 < n) *(float2*)&Y[(size_t)r1 * 64 + col] = o1;
    }
}

// ---------------- launcher ---------------------------------------------------
extern "C" void kernel_launch(void* const* d_in, const int* in_sizes, int n_in,
                              void* d_out, int out_size) {
    const float* x        = (const float*)d_in[0];
    const void*  ei       = d_in[1];                 // int64 or int32; auto-detected
    const float* gcn_w1   = (const float*)d_in[2];
    const float* gcn_b1   = (const float*)d_in[3];
    const float* gcn_w2   = (const float*)d_in[4];
    const float* gcn_b2   = (const float*)d_in[5];
    const float* sage_wl1 = (const float*)d_in[6];
    const float* sage_bl1 = (const float*)d_in[7];
    const float* sage_wr1 = (const float*)d_in[8];
    const float* sage_wl2 = (const float*)d_in[9];
    const float* sage_bl2 = (const float*)d_in[10];
    const float* sage_wr2 = (const float*)d_in[11];
    const float* gln_g    = (const float*)d_in[12];
    const float* gln_b    = (const float*)d_in[13];
    const float* sln_g    = (const float*)d_in[14];
    const float* sln_b    = (const float*)d_in[15];
    const float* proj_w   = (const float*)d_in[16];
    const float* proj_b   = (const float*)d_in[17];
    float*       out      = (float*)d_out;

    int n = in_sizes[0] / 64;
    int e = in_sizes[1] / 2;

    float* bufbase = nullptr;
    cudaGetSymbolAddress((void**)&bufbase, g_buf);
    float* B[6];
    for (int i = 0; i < 6; i++) B[i] = bufbase + (size_t)i * N_MAX * 64;
    __half* halfbase = nullptr;
    cudaGetSymbolAddress((void**)&halfbase, g_half);
    __half* xh  = halfbase;
    __half* g1h = halfbase + (size_t)N_MAX * 64;
    __half* s1h = halfbase + (size_t)2 * N_MAX * 64;

    const size_t sm2 = (size_t)(128 + 64) * 136 * 2 * 2;   // 104448 (K=128 worst case)
    cudaFuncSetAttribute(k_gemm_pair<true>,
                         cudaFuncAttributeMaxDynamicSharedMemorySize, (int)sm2);
    cudaFuncSetAttribute(k_gemm_pair<false>,
                         cudaFuncAttributeMaxDynamicSharedMemorySize, (int)sm2);
    cudaFuncSetAttribute(k_proj,
                         cudaFuncAttributeMaxDynamicSharedMemorySize, (int)sm2);

    int nb1k = (n + 1023) / 1024;
    int gb   = (n + 127) / 128;
    int ab   = (n + 7) / 8;       // warp-per-node blocks (256 thr)

    // CSR build + x fp16 conversion
    k_prep<<<(n * 16 + 255) / 256, 256>>>(ei, x, xh, e, n);
    k_count<<<(e + 255) / 256, 256>>>(ei, e, n);
    k_scan1<<<nb1k, 1024>>>(n);
    k_scan23<<<nb1k, 1024>>>(n, nb1k);
    k_scatter<<<(e + 255) / 256, 256>>>(ei, e, n);

    // Layer 1: fused dual aggregation over xh, then merged layer-1 GEMM pair
    k_agg_dual1<<<ab, 256>>>(xh, B[0], B[1], n);                      // B0=GCN-agg, B1=mean
    k_gemm_pair<true><<<dim3(gb, 2), 256, sm2>>>(
        B[0], gcn_w1, gcn_b1, g1h,
        B[1], sage_wl1, x, sage_wr1, sage_bl1, s1h, n);

    // Layer 2: fused dual aggregation over (g1h, s1h), then merged layer-2 GEMM pair
    k_agg_dual2<<<ab, 256>>>(g1h, s1h, B[0], B[1], n);                // B0=GCN-agg, B1=mean
    k_gemm_pair<false><<<dim3(gb, 2), 256, sm2>>>(
        B[0], gcn_w2, gcn_b2, B[4],
        B[1], sage_wl2, s1h, sage_wr2, sage_bl2, B[5], n);

    // Fused LayerNorm + concat projection (tensor-core)
    k_proj<<<gb, 256, sm2>>>(B[4], B[5], gln_g, gln_b, sln_g, sln_b,
                             proj_w, proj_b, out, n);
}

// round 17
// speedup vs baseline: 1.1533x; 1.0512x over previous
#include <cuda_runtime.h>
#include <cuda_bf16.h>
#include <cuda_fp16.h>
#include <cstdint>

#define N_MAX 100000
#define E_MAX 1250000

// ---------------- scratch (static device allocations; no runtime alloc) -----
__device__ int    g_is64;
__device__ int    g_deg[N_MAX];
__device__ int    g_incl[N_MAX];
__device__ int    g_rowptr[N_MAX];
__device__ int    g_cursor[N_MAX];
__device__ int    g_bsum[256];
__device__ float  g_dinv[N_MAX];
__device__ float  g_cinv[N_MAX];
__device__ int    g_edge[E_MAX];
__device__ float  g_buf[6][(size_t)N_MAX * 64];
__device__ __half g_half[3][(size_t)N_MAX * 64];     // xh, g1h, s1h
// Precomputed B-operand smem images (bf16 hi/lo, padded rows).
// offsets (u32): img0 gcn_w1 @0 (64*36), img1 sageL1 @2304 (64*68),
// img2 gcn_w2 @6656 (64*36), img3 sageL2 @8960 (64*68), img4 proj @13312 (64*68)
#define WOFF0 0
#define WOFF1 2304
#define WOFF2 6656
#define WOFF3 8960
#define WOFF4 13312
__device__ uint32_t g_wimg_hi[17664];
__device__ uint32_t g_wimg_lo[17664];

// ---------------- bf16 split helper ------------------------------------------
__device__ __forceinline__ void split_pack(float x, float y, uint32_t& hi, uint32_t& lo) {
    __nv_bfloat162 h = __floats2bfloat162_rn(x, y);
    __nv_bfloat162 l = __floats2bfloat162_rn(x - __bfloat162float(h.x),
                                             y - __bfloat162float(h.y));
    hi = *(uint32_t*)&h;
    lo = *(uint32_t*)&l;
}

// ---------------- precompute W hi/lo smem images ------------------------------
__global__ void k_prepw(const float* __restrict__ w1g,
                        const float* __restrict__ wl1, const float* __restrict__ wr1,
                        const float* __restrict__ w2g,
                        const float* __restrict__ wl2, const float* __restrict__ wr2,
                        const float* __restrict__ wp) {
    int img = blockIdx.y;
    int KT  = (img == 0 || img == 2) ? 64 : 128;
    int KH  = KT / 2;
    int KPW = KH + 4;
    int total = 64 * KH;
    int t = blockIdx.x * 256 + threadIdx.x;
    if (t >= total) return;
    int nn = t / KH;
    int p  = t % KH;
    int k0 = 2 * p;
    const float* A; const float* B = nullptr; uint32_t off;
    switch (img) {
        case 0:  A = w1g;                     off = WOFF0; break;
        case 1:  A = wl1; B = wr1;            off = WOFF1; break;
        case 2:  A = w2g;                     off = WOFF2; break;
        case 3:  A = wl2; B = wr2;            off = WOFF3; break;
        default: A = wp;  B = wp + 64 * 64;   off = WOFF4; break;
    }
    float x0 = (k0 < 64)     ? A[k0 * 64 + nn]       : B[(k0 - 64) * 64 + nn];
    float x1 = (k0 + 1 < 64) ? A[(k0 + 1) * 64 + nn] : B[(k0 + 1 - 64) * 64 + nn];
    uint32_t hi, lo;
    split_pack(x0, x1, hi, lo);
    g_wimg_hi[off + nn * KPW + p] = hi;
    g_wimg_lo[off + nn * KPW + p] = lo;
}

// ---------------- fused: zero degrees + x->fp16 + x->hi/lo + dtype detect ----
__global__ void k_prep(const void* __restrict__ ei, const float* __restrict__ x,
                       __half* __restrict__ xh, uint2* __restrict__ xpk, int e, int n) {
    int i = blockIdx.x * blockDim.x + threadIdx.x;
    if (i < n) g_deg[i] = 0;
    int total = n * 16;   // float4 quads
    if (i < total) {
        float4 v = ((const float4*)x)[i];
        __half2 h0 = __floats2half2_rn(v.x, v.y);
        __half2 h1 = __floats2half2_rn(v.z, v.w);
        ((__half2*)xh)[i * 2]     = h0;
        ((__half2*)xh)[i * 2 + 1] = h1;
        uint32_t ph0, pl0, ph1, pl1;
        split_pack(v.x, v.y, ph0, pl0);
        split_pack(v.z, v.w, ph1, pl1);
        xpk[i * 2]     = make_uint2(ph0, pl0);
        xpk[i * 2 + 1] = make_uint2(ph1, pl1);
    }
    if (blockIdx.x == 0) {
        __shared__ int bad;
        if (threadIdx.x == 0) bad = 0;
        __syncthreads();
        const long long* p = (const long long*)ei;
        int m = e < 2048 ? e : 2048;
        for (int j = threadIdx.x; j < m; j += blockDim.x) {
            long long v = p[j];
            if (v < 0 || v >= (long long)n) bad = 1;
        }
        __syncthreads();
        if (threadIdx.x == 0) g_is64 = bad ? 0 : 1;
    }
}

__device__ __forceinline__ int ld_idx(const void* __restrict__ ei, int is64,
                                      long long pos, int n) {
    long long v = is64 ? ((const long long*)ei)[pos]
                       : (long long)((const int*)ei)[pos];
    int s = (int)v;
    if ((unsigned)s >= (unsigned)n) s = 0;
    return s;
}

// ---------------- CSR build --------------------------------------------------
__global__ void k_count(const void* __restrict__ ei, int e, int n) {
    int i = blockIdx.x * blockDim.x + threadIdx.x;
    if (i >= e) return;
    int is64 = g_is64;
    int d = ld_idx(ei, is64, (long long)e + i, n);
    atomicAdd(&g_deg[d], 1);
}

__global__ void k_scan1(int n) {
    __shared__ int sh[1024];
    int t = threadIdx.x;
    int i = blockIdx.x * 1024 + t;
    int v = (i < n) ? g_deg[i] : 0;
    sh[t] = v;
    __syncthreads();
    for (int off = 1; off < 1024; off <<= 1) {
        int add = (t >= off) ? sh[t - off] : 0;
        __syncthreads();
        sh[t] += add;
        __syncthreads();
    }
    if (i < n) g_incl[i] = sh[t];
    if (t == 1023) g_bsum[blockIdx.x] = sh[1023];
}

__global__ void k_scan23(int n, int nb) {
    __shared__ int sh[256];
    __shared__ int orig[256];
    int t = threadIdx.x;
    if (t < 256) {
        int v = (t < nb) ? g_bsum[t] : 0;
        sh[t] = v;
        orig[t] = v;
    }
    __syncthreads();
    for (int off = 1; off < 256; off <<= 1) {
        int add = (t < 256 && t >= off) ? sh[t - off] : 0;
        __syncthreads();
        if (t < 256) sh[t] += add;
        __syncthreads();
    }
    int i = blockIdx.x * 1024 + t;
    if (i >= n) return;
    int boff = sh[blockIdx.x] - orig[blockIdx.x];
    int d  = g_deg[i];
    int rp = g_incl[i] - d + boff;
    g_rowptr[i] = rp;
    g_cursor[i] = rp;
    g_dinv[i] = rsqrtf((float)d + 1.0f);
    g_cinv[i] = 1.0f / fmaxf((float)d, 1.0f);
}

__global__ void k_scatter(const void* __restrict__ ei, int e, int n) {
    int i = blockIdx.x * blockDim.x + threadIdx.x;
    if (i >= e) return;
    int is64 = g_is64;
    int s = ld_idx(ei, is64, i, n);
    int d = ld_idx(ei, is64, (long long)e + i, n);
    int pos = atomicAdd(&g_cursor[d], 1);
    g_edge[pos] = s;
}

// ---------------- fused dual aggregations (warp per node, 2 feats/lane) -----
// R13 loop form; outputs written as packed bf16 (hi,lo) uint2 — same bytes.
__global__ void k_agg_dual1(const __half* __restrict__ xh,
                            uint2* __restrict__ outG, uint2* __restrict__ outM, int n) {
    int gw   = (blockIdx.x * blockDim.x + threadIdx.x) >> 5;
    int lane = threadIdx.x & 31;
    if (gw >= n) return;
    int start = g_rowptr[gw];
    int cnt   = g_deg[gw];
    float wx = 0.f, wy = 0.f, mx = 0.f, my = 0.f;
    int src = (cnt > 0) ? g_edge[start] : 0;
    for (int e = 0; e < cnt; e++) {
        int cur = src;
        if (e + 1 < cnt) src = g_edge[start + e + 1];
        float ds = g_dinv[cur];
        float2 v = __half22float2(*(const __half2*)(xh + (size_t)cur * 64 + lane * 2));
        wx = fmaf(ds, v.x, wx);
        wy = fmaf(ds, v.y, wy);
        mx += v.x;
        my += v.y;
    }
    float dd = g_dinv[gw];
    float ci = g_cinv[gw];
    float2 xv = __half22float2(*(const __half2*)(xh + (size_t)gw * 64 + lane * 2));
    float ogx = fmaf(dd, wx, dd * dd * xv.x);
    float ogy = fmaf(dd, wy, dd * dd * xv.y);
    uint32_t h, l;
    split_pack(ogx, ogy, h, l);
    outG[gw * 32 + lane] = make_uint2(h, l);
    split_pack(mx * ci, my * ci, h, l);
    outM[gw * 32 + lane] = make_uint2(h, l);
}

__global__ void k_agg_dual2(const __half* __restrict__ g1h, const __half* __restrict__ s1h,
                            uint2* __restrict__ outG, uint2* __restrict__ outM, int n) {
    int gw   = (blockIdx.x * blockDim.x + threadIdx.x) >> 5;
    int lane = threadIdx.x & 31;
    if (gw >= n) return;
    int start = g_rowptr[gw];
    int cnt   = g_deg[gw];
    float wx = 0.f, wy = 0.f, mx = 0.f, my = 0.f;
    int src = (cnt > 0) ? g_edge[start] : 0;
    for (int e = 0; e < cnt; e++) {
        int cur = src;
        if (e + 1 < cnt) src = g_edge[start + e + 1];
        float ds = g_dinv[cur];
        float2 gv = __half22float2(*(const __half2*)(g1h + (size_t)cur * 64 + lane * 2));
        float2 sv = __half22float2(*(const __half2*)(s1h + (size_t)cur * 64 + lane * 2));
        wx = fmaf(ds, gv.x, wx);
        wy = fmaf(ds, gv.y, wy);
        mx += sv.x;
        my += sv.y;
    }
    float dd = g_dinv[gw];
    float ci = g_cinv[gw];
    float2 gsv = __half22float2(*(const __half2*)(g1h + (size_t)gw * 64 + lane * 2));
    float ogx = fmaf(dd, wx, dd * dd * gsv.x);
    float ogy = fmaf(dd, wy, dd * dd * gsv.y);
    uint32_t h, l;
    split_pack(ogx, ogy, h, l);
    outG[gw * 32 + lane] = make_uint2(h, l);
    split_pack(mx * ci, my * ci, h, l);
    outM[gw * 32 + lane] = make_uint2(h, l);
}

// ---------------- tensor-core GEMM via split-bf16 (3-term) -------------------
__device__ __forceinline__ void mma_bf16(float* c,
                                         uint32_t a0, uint32_t a1, uint32_t a2, uint32_t a3,
                                         uint32_t b0, uint32_t b1) {
    asm volatile(
        "mma.sync.aligned.m16n8k16.row.col.f32.bf16.bf16.f32 "
        "{%0,%1,%2,%3}, {%4,%5,%6,%7}, {%8,%9}, {%0,%1,%2,%3};\n"
        : "+f"(c[0]), "+f"(c[1]), "+f"(c[2]), "+f"(c[3])
        : "r"(a0), "r"(a1), "r"(a2), "r"(a3), "r"(b0), "r"(b1));
}

// Body: Y = act( Xa@Wa [+ Xb@Wb] + bias ).
// Xa: packed hi/lo uint4 rows (16 uint4/row, covers k<64).
// Xb: packed uint4 rows (k>=64) or fp16 rows (XB_HALF).
// W: precomputed hi/lo smem image (flat copy).
template <bool DUAL, bool RELU, bool XB_HALF, bool OUT_HALF>
__device__ __forceinline__ void gemm_body(
        const uint4* __restrict__ Xa, const uint32_t* __restrict__ wimg_hi,
        const uint32_t* __restrict__ wimg_lo, const void* __restrict__ Xb,
        const float* __restrict__ bias, void* __restrict__ Yv, int n) {
    constexpr int KT  = DUAL ? 128 : 64;
    constexpr int KPW = KT / 2 + 4;
    extern __shared__ uint32_t smu[];
    uint32_t* Ahi = smu;
    uint32_t* Alo = Ahi + 128 * KPW;
    uint32_t* Bhi = Alo + 128 * KPW;
    uint32_t* Blo = Bhi + 64 * KPW;

    int tid  = threadIdx.x;
    int base = blockIdx.x * 128;

    // W staging: flat uint4 copy of precomputed image
    for (int i = tid; i < (64 * KPW) / 4; i += 256) {
        ((uint4*)Bhi)[i] = ((const uint4*)wimg_hi)[i];
        ((uint4*)Blo)[i] = ((const uint4*)wimg_lo)[i];
    }
    // X staging: one LDG.128 per 4 values, no conversion (except fp16 Xb)
    constexpr int KQ4 = KT / 4;
    for (int i = tid; i < 128 * KQ4; i += 256) {
        int r  = i / KQ4;
        int kq = i % KQ4;
        int row = base + r;
        uint4 v = make_uint4(0u, 0u, 0u, 0u);
        if (row < n) {
            if (DUAL && kq >= 16) {
                if (XB_HALF) {
                    const __half* xb = (const __half*)Xb + (size_t)row * 64 + (kq - 16) * 4;
                    float2 fa = __half22float2(*(const __half2*)xb);
                    float2 fb = __half22float2(*(const __half2*)(xb + 2));
                    split_pack(fa.x, fa.y, v.x, v.y);
                    split_pack(fb.x, fb.y, v.z, v.w);
                } else {
                    v = ((const uint4*)Xb)[(size_t)row * 16 + (kq - 16)];
                }
            } else {
                v = Xa[(size_t)row * 16 + kq];
            }
        }
        int wo = r * KPW + kq * 2;
        Ahi[wo]     = v.x;
        Ahi[wo + 1] = v.z;
        Alo[wo]     = v.y;
        Alo[wo + 1] = v.w;
    }
    __syncthreads();

    int warp  = tid >> 5;
    int lane  = tid & 31;
    int tq    = lane >> 2;
    int tc    = lane & 3;
    int rbase = warp * 16;

    float acc[8][4];
#pragma unroll
    for (int nt = 0; nt < 8; nt++)
#pragma unroll
        for (int c = 0; c < 4; c++) acc[nt][c] = 0.f;

#pragma unroll
    for (int kk = 0; kk < KT / 16; kk++) {
        int colw = kk * 8 + tc;
        int ra = (rbase + tq) * KPW + colw;
        int rb = ra + 8 * KPW;
        uint32_t ah0 = Ahi[ra], ah1 = Ahi[rb], ah2 = Ahi[ra + 4], ah3 = Ahi[rb + 4];
        uint32_t al0 = Alo[ra], al1 = Alo[rb], al2 = Alo[ra + 4], al3 = Alo[rb + 4];
#pragma unroll
        for (int nt = 0; nt < 8; nt++) {
            int nb = (nt * 8 + tq) * KPW + colw;
            uint32_t bh0 = Bhi[nb], bh1 = Bhi[nb + 4];
            uint32_t bl0 = Blo[nb], bl1 = Blo[nb + 4];
            mma_bf16(acc[nt], ah0, ah1, ah2, ah3, bh0, bh1);
            mma_bf16(acc[nt], ah0, ah1, ah2, ah3, bl0, bl1);
            mma_bf16(acc[nt], al0, al1, al2, al3, bh0, bh1);
        }
    }

    int r0 = base + rbase + tq;
    int r1 = r0 + 8;
#pragma unroll
    for (int nt = 0; nt < 8; nt++) {
        int col = nt * 8 + 2 * tc;
        float2 bv = *(const float2*)&bias[col];
        float2 o0 = make_float2(acc[nt][0] + bv.x, acc[nt][1] + bv.y);
        float2 o1 = make_float2(acc[nt][2] + bv.x, acc[nt][3] + bv.y);
        if (RELU) {
            o0.x = fmaxf(o0.x, 0.f); o0.y = fmaxf(o0.y, 0.f);
            o1.x = fmaxf(o1.x, 0.f); o1.y = fmaxf(o1.y, 0.f);
        }
        if (OUT_HALF) {
            __half* Y = (__half*)Yv;
            if (r0 < n) *(__half2*)&Y[(size_t)r0 * 64 + col] = __floats2half2_rn(o0.x, o0.y);
            if (r1 < n) *(__half2*)&Y[(size_t)r1 * 64 + col] = __floats2half2_rn(o1.x, o1.y);
        } else {
            float* Y = (float*)Yv;
            if (r0 < n) *(float2*)&Y[(size_t)r0 * 64 + col] = o0;
            if (r1 < n) *(float2*)&Y[(size_t)r1 * 64 + col] = o1;
        }
    }
}

// Merged per-layer GEMM pair: blockIdx.y==0 -> GCN (K=64); ==1 -> SAGE dual (K=128).
template <bool L1>
__global__ void __launch_bounds__(256)
k_gemm_pair(const uint4* __restrict__ Xg, const uint32_t* __restrict__ wg_hi,
            const uint32_t* __restrict__ wg_lo, const float* __restrict__ bg,
            void* __restrict__ Yg,
            const uint4* __restrict__ Xs, const uint32_t* __restrict__ ws_hi,
            const uint32_t* __restrict__ ws_lo, const void* __restrict__ Xb,
            const float* __restrict__ bs, void* __restrict__ Ys, int n) {
    if (blockIdx.y == 0) {
        gemm_body<false, L1, false, L1>(Xg, wg_hi, wg_lo, nullptr, bg, Yg, n);
    } else {
        gemm_body<true, L1, !L1, L1>(Xs, ws_hi, ws_lo, Xb, bs, Ys, n);
    }
}

// ---------------- projection GEMM with fused per-branch LayerNorm -----------
__global__ void k_proj(const float* __restrict__ G, const float* __restrict__ S,
                       const float* __restrict__ gg, const float* __restrict__ gb,
                       const float* __restrict__ sg, const float* __restrict__ sb,
                       const uint32_t* __restrict__ wimg_hi,
                       const uint32_t* __restrict__ wimg_lo,
                       const float* __restrict__ bias,
                       float* __restrict__ Y, int n) {
    constexpr int KT = 128, KPW = 68;
    extern __shared__ uint32_t smu[];
    uint32_t* Ahi = smu;
    uint32_t* Alo = Ahi + 128 * KPW;
    uint32_t* Bhi = Alo + 128 * KPW;
    uint32_t* Blo = Bhi + 64 * KPW;

    int tid  = threadIdx.x;
    int warp = tid >> 5;
    int lane = tid & 31;
    int base = blockIdx.x * 128;

    for (int i = tid; i < (64 * KPW) / 4; i += 256) {
        ((uint4*)Bhi)[i] = ((const uint4*)wimg_hi)[i];
        ((uint4*)Blo)[i] = ((const uint4*)wimg_lo)[i];
    }

    float2 ggv = *(const float2*)&gg[lane * 2];
    float2 gbv = *(const float2*)&gb[lane * 2];
    float2 sgv = *(const float2*)&sg[lane * 2];
    float2 sbv = *(const float2*)&sb[lane * 2];
    for (int it = 0; it < 16; it++) {
        int r   = warp * 16 + it;
        int row = base + r;
        float2 gv = make_float2(0.f, 0.f), sv = make_float2(0.f, 0.f);
        if (row < n) {
            gv = *(const float2*)(G + (size_t)row * 64 + lane * 2);
            sv = *(const float2*)(S + (size_t)row * 64 + lane * 2);
        }
        float sgm = gv.x + gv.y, qg = gv.x * gv.x + gv.y * gv.y;
        float ssm = sv.x + sv.y, qs = sv.x * sv.x + sv.y * sv.y;
#pragma unroll
        for (int o = 16; o > 0; o >>= 1) {
            sgm += __shfl_xor_sync(0xffffffffu, sgm, o);
            qg  += __shfl_xor_sync(0xffffffffu, qg, o);
            ssm += __shfl_xor_sync(0xffffffffu, ssm, o);
            qs  += __shfl_xor_sync(0xffffffffu, qs, o);
        }
        float mug  = sgm * (1.0f / 64.0f);
        float varg = fmaxf(qg * (1.0f / 64.0f) - mug * mug, 0.f);
        float rg   = rsqrtf(varg + 1e-5f);
        float mus  = ssm * (1.0f / 64.0f);
        float vars = fmaxf(qs * (1.0f / 64.0f) - mus * mus, 0.f);
        float rs   = rsqrtf(vars + 1e-5f);
        float ogx = (gv.x - mug) * rg * ggv.x + gbv.x;
        float ogy = (gv.y - mug) * rg * ggv.y + gbv.y;
        float osx = (sv.x - mus) * rs * sgv.x + sbv.x;
        float osy = (sv.y - mus) * rs * sgv.y + sbv.y;
        uint32_t h, l;
        split_pack(ogx, ogy, h, l);
        Ahi[r * KPW + lane] = h;
        Alo[r * KPW + lane] = l;
        split_pack(osx, osy, h, l);
        Ahi[r * KPW + 32 + lane] = h;
        Alo[r * KPW + 32 + lane] = l;
    }
    __syncthreads();

    int tq    = lane >> 2;
    int tc    = lane & 3;
    int rbase = warp * 16;

    float acc[8][4];
#pragma unroll
    for (int nt = 0; nt < 8; nt++)
#pragma unroll
        for (int c = 0; c < 4; c++) acc[nt][c] = 0.f;

#pragma unroll
    for (int kk = 0; kk < KT / 16; kk++) {
        int colw = kk * 8 + tc;
        int ra = (rbase + tq) * KPW + colw;
        int rb = ra + 8 * KPW;
        uint32_t ah0 = Ahi[ra], ah1 = Ahi[rb], ah2 = Ahi[ra + 4], ah3 = Ahi[rb + 4];
        uint32_t al0 = Alo[ra], al1 = Alo[rb], al2 = Alo[ra + 4], al3 = Alo[rb + 4];
#pragma unroll
        for (int nt = 0; nt < 8; nt++) {
            int nb = (nt * 8 + tq) * KPW + colw;
            uint32_t bh0 = Bhi[nb], bh1 = Bhi[nb + 4];
            uint32_t bl0 = Blo[nb], bl1 = Blo[nb + 4];
            mma_bf16(acc[nt], ah0, ah1, ah2, ah3, bh0, bh1);
            mma_bf16(acc[nt], ah0, ah1, ah2, ah3, bl0, bl1);
            mma_bf16(acc[nt], al0, al1, al2, al3, bh0, bh1);
        }
    }

    int r0 = base + rbase + tq;
    int r1 = r0 + 8;
#pragma unroll
    for (int nt = 0; nt < 8; nt++) {
        int col = nt * 8 + 2 * tc;
        float2 bv = *(const float2*)&bias[col];
        float2 o0 = make_float2(acc[nt][0] + bv.x, acc[nt][1] + bv.y);
        float2 o1 = make_float2(acc[nt][2] + bv.x, acc[nt][3] + bv.y);
        if (r0 < n) *(float2*)&Y[(size_t)r0 * 64 + col] = o0;
        if (r1 < n) *(float2*)&Y[(size_t)r1 * 64 + col] = o1;
    }
}

// ---------------- launcher ---------------------------------------------------
extern "C" void kernel_launch(void* const* d_in, const int* in_sizes, int n_in,
                              void* d_out, int out_size) {
    const float* x        = (const float*)d_in[0];
    const void*  ei       = d_in[1];
    const float* gcn_w1   = (const float*)d_in[2];
    const float* gcn_b1   = (const float*)d_in[3];
    const float* gcn_w2   = (const float*)d_in[4];
    const float* gcn_b2   = (const float*)d_in[5];
    const float* sage_wl1 = (const float*)d_in[6];
    const float* sage_bl1 = (const float*)d_in[7];
    const float* sage_wr1 = (const float*)d_in[8];
    const float* sage_wl2 = (const float*)d_in[9];
    const float* sage_bl2 = (const float*)d_in[10];
    const float* sage_wr2 = (const float*)d_in[11];
    const float* gln_g    = (const float*)d_in[12];
    const float* gln_b    = (const float*)d_in[13];
    const float* sln_g    = (const float*)d_in[14];
    const float* sln_b    = (const float*)d_in[15];
    const float* proj_w   = (const float*)d_in[16];
    const float* proj_b   = (const float*)d_in[17];
    float*       out      = (float*)d_out;

    int n = in_sizes[0] / 64;
    int e = in_sizes[1] / 2;

    float* bufbase = nullptr;
    cudaGetSymbolAddress((void**)&bufbase, g_buf);
    float* B[6];
    for (int i = 0; i < 6; i++) B[i] = bufbase + (size_t)i * N_MAX * 64;
    __half* halfbase = nullptr;
    cudaGetSymbolAddress((void**)&halfbase, g_half);
    __half* xh  = halfbase;
    __half* g1h = halfbase + (size_t)N_MAX * 64;
    __half* s1h = halfbase + (size_t)2 * N_MAX * 64;
    uint32_t* whi = nullptr; uint32_t* wlo = nullptr;
    cudaGetSymbolAddress((void**)&whi, g_wimg_hi);
    cudaGetSymbolAddress((void**)&wlo, g_wimg_lo);

    // packed hi/lo X operands (uint2 per value-pair; alias fp32 scratch regions)
    uint2* B0pk = (uint2*)B[0];
    uint2* B1pk = (uint2*)B[1];
    uint2* xpk  = (uint2*)B[2];

    const size_t sm2 = (size_t)(128 + 64) * 136 * 2 * 2;   // 104448 (K=128 worst case)
    cudaFuncSetAttribute(k_gemm_pair<true>,
                         cudaFuncAttributeMaxDynamicSharedMemorySize, (int)sm2);
    cudaFuncSetAttribute(k_gemm_pair<false>,
                         cudaFuncAttributeMaxDynamicSharedMemorySize, (int)sm2);
    cudaFuncSetAttribute(k_proj,
                         cudaFuncAttributeMaxDynamicSharedMemorySize, (int)sm2);

    int nb1k = (n + 1023) / 1024;
    int gb   = (n + 127) / 128;
    int ab   = (n + 7) / 8;

    // W images + CSR build + x conversions
    k_prepw<<<dim3(16, 5), 256>>>(gcn_w1, sage_wl1, sage_wr1,
                                  gcn_w2, sage_wl2, sage_wr2, proj_w);
    k_prep<<<(n * 16 + 255) / 256, 256>>>(ei, x, xh, xpk, e, n);
    k_count<<<(e + 255) / 256, 256>>>(ei, e, n);
    k_scan1<<<nb1k, 1024>>>(n);
    k_scan23<<<nb1k, 1024>>>(n, nb1k);
    k_scatter<<<(e + 255) / 256, 256>>>(ei, e, n);

    // Layer 1: fused dual aggregation over xh, then merged layer-1 GEMM pair
    k_agg_dual1<<<ab, 256>>>(xh, B0pk, B1pk, n);
    k_gemm_pair<true><<<dim3(gb, 2), 256, sm2>>>(
        (const uint4*)B0pk, whi + WOFF0, wlo + WOFF0, gcn_b1, g1h,
        (const uint4*)B1pk, whi + WOFF1, wlo + WOFF1, xpk, sage_bl1, s1h, n);

    // Layer 2: fused dual aggregation over (g1h, s1h), then merged layer-2 GEMM pair
    k_agg_dual2<<<ab, 256>>>(g1h, s1h, B0pk, B1pk, n);
    k_gemm_pair<false><<<dim3(gb, 2), 256, sm2>>>(
        (const uint4*)B0pk, whi + WOFF2, wlo + WOFF2, gcn_b2, B[4],
        (const uint4*)B1pk, whi + WOFF3, wlo + WOFF3, s1h, sage_bl2, B[5], n);

    // Fused LayerNorm + concat projection (tensor-core)
    k_proj<<<gb, 256, sm2>>>(B[4], B[5], gln_g, gln_b, sln_g, sln_b,
                             whi + WOFF4, wlo + WOFF4, proj_b, out, n);
}